// round 1
// baseline (speedup 1.0000x reference)
#include <cuda_runtime.h>

#define Bn   16
#define Cc   512
#define HWn  1024
#define CPG  16     // channels per group (512/32)
#define NH   8
#define DH   64

// Scratch (static device allocations — allowed; no cudaMalloc)
__device__ float g_h[Bn * Cc * HWn];                 // group-normed x     (33.5 MB)
__device__ float g_qkv[Bn * NH * 3 * HWn * DH];      // q/k/v [bh][p][s][c] (100.7 MB)
__device__ float g_attn[Bn * Cc * HWn];              // attn out, proj-input layout (33.5 MB)

// ---------------------------------------------------------------------------
// Kernel 1: GroupNorm. One block per (b, group). 16384 elems per group.
// ---------------------------------------------------------------------------
__global__ __launch_bounds__(256) void gn_kernel(const float* __restrict__ x,
                                                 const float* __restrict__ gamma,
                                                 const float* __restrict__ beta) {
    int b = blockIdx.x >> 5;
    int g = blockIdx.x & 31;
    size_t base = (size_t)(b * Cc + g * CPG) * HWn;
    const float4* xp = (const float4*)(x + base);
    float4* hp = (float4*)(g_h + base);
    const int N4 = CPG * HWn / 4;   // 4096

    float s = 0.f, ss = 0.f;
    for (int i = threadIdx.x; i < N4; i += 256) {
        float4 v = xp[i];
        s  += v.x + v.y + v.z + v.w;
        ss += v.x * v.x + v.y * v.y + v.z * v.z + v.w * v.w;
    }
    __shared__ float rs_[8], rss_[8];
    #pragma unroll
    for (int o = 16; o; o >>= 1) {
        s  += __shfl_xor_sync(0xffffffffu, s, o);
        ss += __shfl_xor_sync(0xffffffffu, ss, o);
    }
    int wid = threadIdx.x >> 5, lid = threadIdx.x & 31;
    if (lid == 0) { rs_[wid] = s; rss_[wid] = ss; }
    __syncthreads();
    if (threadIdx.x < 32) {
        s = rs_[lid & 7]; ss = rss_[lid & 7];
        #pragma unroll
        for (int o = 4; o; o >>= 1) {
            s  += __shfl_xor_sync(0xffffffffu, s, o);
            ss += __shfl_xor_sync(0xffffffffu, ss, o);
        }
        if (lid == 0) { rs_[0] = s; rss_[0] = ss; }
    }
    __syncthreads();
    float mean = rs_[0] * (1.f / 16384.f);
    float var  = rss_[0] * (1.f / 16384.f) - mean * mean;
    float inv  = rsqrtf(var + 1e-5f);

    for (int i = threadIdx.x; i < N4; i += 256) {
        int c = g * CPG + (i >> 8);            // (i*4)/1024
        float ga = gamma[c] * inv;
        float be = beta[c] - mean * ga;
        float4 v = xp[i];
        float4 o4;
        o4.x = v.x * ga + be; o4.y = v.y * ga + be;
        o4.z = v.z * ga + be; o4.w = v.w * ga + be;
        hp[i] = o4;
    }
}

// ---------------------------------------------------------------------------
// Kernel 2: qkv = W_qkv @ h  per batch. Tile 64(s) x 64(o) x 16(k).
// Epilogue writes [bh][part][s][c] directly (c contiguous, coalesced float4).
// Each 64-wide o-tile maps to exactly one (head, part) since 192 = 3*64.
// ---------------------------------------------------------------------------
__global__ __launch_bounds__(256) void qkv_gemm_kernel(const float* __restrict__ W,
                                                       const float* __restrict__ bias) {
    int b  = blockIdx.z;
    int o0 = blockIdx.y << 6;
    int n0 = blockIdx.x << 6;
    const float* hb = g_h + (size_t)b * Cc * HWn;

    __shared__ float As[16][64];   // h tile   [k][n]   natural
    __shared__ float Bs[16][64];   // W tile   [k][m]   swizzled: col = m ^ (k<<2)

    int tid = threadIdx.x;
    int ty = tid >> 4, tx = tid & 15;
    int mrow = tid >> 2, kq = tid & 3;

    float acc[4][4];
    #pragma unroll
    for (int i = 0; i < 4; i++)
        #pragma unroll
        for (int j = 0; j < 4; j++) acc[i][j] = 0.f;

    for (int k0 = 0; k0 < Cc; k0 += 16) {
        #pragma unroll
        for (int it = 0; it < 4; it++) {
            int lin = tid + it * 256;
            int n = lin & 63, k = lin >> 6;
            As[k][n] = hb[(size_t)(k0 + k) * HWn + n0 + n];
        }
        {
            float4 w4 = *(const float4*)&W[(size_t)(o0 + mrow) * Cc + k0 + (kq << 2)];
            #pragma unroll
            for (int u = 0; u < 4; u++) {
                int k = (kq << 2) + u;
                Bs[k][mrow ^ (k << 2)] = (&w4.x)[u];
            }
        }
        __syncthreads();
        #pragma unroll
        for (int k = 0; k < 16; k++) {
            float4 a  = *(const float4*)&As[k][ty << 2];
            float4 bv = *(const float4*)&Bs[k][(tx << 2) ^ (k << 2)];
            float av[4] = {a.x, a.y, a.z, a.w};
            float bb[4] = {bv.x, bv.y, bv.z, bv.w};
            #pragma unroll
            for (int i = 0; i < 4; i++)
                #pragma unroll
                for (int j = 0; j < 4; j++)
                    acc[i][j] = fmaf(av[i], bb[j], acc[i][j]);
        }
        __syncthreads();
    }

    int head = o0 / 192;
    int part = (o0 - head * 192) >> 6;
    float* dst = g_qkv + (size_t)((b * NH + head) * 3 + part) * HWn * DH;
    float4 bi = *(const float4*)&bias[o0 + (tx << 2)];
    #pragma unroll
    for (int i = 0; i < 4; i++) {
        int s = n0 + (ty << 2) + i;
        float4 o4;
        o4.x = acc[i][0] + bi.x; o4.y = acc[i][1] + bi.y;
        o4.z = acc[i][2] + bi.z; o4.w = acc[i][3] + bi.w;
        *(float4*)&dst[(size_t)s * DH + (tx << 2)] = o4;
    }
}

// ---------------------------------------------------------------------------
// Kernel 3: flash attention. Block = (bh, 64-query tile). 64-key tiles, 16 of them.
// Register-blocked 4x4 micro-tiles; XOR-swizzled transposed smem (conflict-free
// LDS.128 inner loops). Online softmax via shfl over 16-lane row groups.
// Epilogue applies the reference's head-major scramble: i = head'*16 + b'.
// ---------------------------------------------------------------------------
__global__ __launch_bounds__(256) void attn_kernel() {
    int bh = blockIdx.y;
    int q0 = blockIdx.x << 6;
    int tid = threadIdx.x;
    int ty = tid >> 4, tx = tid & 15;

    __shared__ float qT[64][64];   // [d][r]  swizzled col = r ^ ((d&15)<<2)
    __shared__ float kb[64][64];   // kT [d][c] swizzled; reused as pT [c][r]; reused as outT [d][r]
    __shared__ float vs[64][64];   // [c][d]  natural

    const float* qp = g_qkv + ((size_t)bh * 3 * HWn + q0) * DH;
    const float* kp = g_qkv + (size_t)(bh * 3 + 1) * HWn * DH;
    const float* vp = g_qkv + (size_t)(bh * 3 + 2) * HWn * DH;
    const float scale = 0.044194173824159216f;   // 512^-0.5 (k scaled, as in reference)

    #pragma unroll
    for (int it = 0; it < 4; it++) {
        int lin = tid + it * 256;
        int r = lin >> 4, dq = lin & 15;
        float4 v4 = *(const float4*)&qp[r * DH + (dq << 2)];
        #pragma unroll
        for (int u = 0; u < 4; u++) {
            int d = (dq << 2) + u;
            qT[d][r ^ ((d & 15) << 2)] = (&v4.x)[u];
        }
    }

    float m_[4], l_[4], acc[4][4];
    #pragma unroll
    for (int i = 0; i < 4; i++) {
        m_[i] = -1e30f; l_[i] = 0.f;
        #pragma unroll
        for (int j = 0; j < 4; j++) acc[i][j] = 0.f;
    }

    for (int t = 0; t < 16; t++) {
        __syncthreads();                       // kb/vs free (prev PV done; q stores done)
        const float* kpt = kp + t * 64 * DH;
        const float* vpt = vp + t * 64 * DH;
        #pragma unroll
        for (int it = 0; it < 4; it++) {
            int lin = tid + it * 256;
            int c = lin >> 4, dq = lin & 15;
            float4 k4 = *(const float4*)&kpt[c * DH + (dq << 2)];
            #pragma unroll
            for (int u = 0; u < 4; u++) {
                int d = (dq << 2) + u;
                kb[d][c ^ ((d & 15) << 2)] = (&k4.x)[u] * scale;
            }
            float4 v4 = *(const float4*)&vpt[c * DH + (dq << 2)];
            *(float4*)&vs[c][dq << 2] = v4;
        }
        __syncthreads();

        // scores: S = Q @ K^T   (rows ty, cols tx)
        float s4[4][4];
        #pragma unroll
        for (int i = 0; i < 4; i++)
            #pragma unroll
            for (int j = 0; j < 4; j++) s4[i][j] = 0.f;
        #pragma unroll 8
        for (int d = 0; d < 64; d++) {
            int sw = (d & 15) << 2;
            float4 a  = *(const float4*)&qT[d][(ty << 2) ^ sw];
            float4 bq = *(const float4*)&kb[d][(tx << 2) ^ sw];
            float av[4] = {a.x, a.y, a.z, a.w};
            float bb[4] = {bq.x, bq.y, bq.z, bq.w};
            #pragma unroll
            for (int i = 0; i < 4; i++)
                #pragma unroll
                for (int j = 0; j < 4; j++)
                    s4[i][j] = fmaf(av[i], bb[j], s4[i][j]);
        }

        // online softmax per row (16 tx lanes share a row; shfl stays in 16-lane half)
        #pragma unroll
        for (int i = 0; i < 4; i++) {
            float mx = fmaxf(fmaxf(s4[i][0], s4[i][1]), fmaxf(s4[i][2], s4[i][3]));
            mx = fmaxf(mx, __shfl_xor_sync(0xffffffffu, mx, 1));
            mx = fmaxf(mx, __shfl_xor_sync(0xffffffffu, mx, 2));
            mx = fmaxf(mx, __shfl_xor_sync(0xffffffffu, mx, 4));
            mx = fmaxf(mx, __shfl_xor_sync(0xffffffffu, mx, 8));
            float mn = fmaxf(m_[i], mx);
            float al = __expf(m_[i] - mn);
            float rs = 0.f;
            #pragma unroll
            for (int j = 0; j < 4; j++) { s4[i][j] = __expf(s4[i][j] - mn); rs += s4[i][j]; }
            rs += __shfl_xor_sync(0xffffffffu, rs, 1);
            rs += __shfl_xor_sync(0xffffffffu, rs, 2);
            rs += __shfl_xor_sync(0xffffffffu, rs, 4);
            rs += __shfl_xor_sync(0xffffffffu, rs, 8);
            l_[i] = l_[i] * al + rs;
            m_[i] = mn;
            #pragma unroll
            for (int j = 0; j < 4; j++) acc[i][j] *= al;
        }

        __syncthreads();                       // all done reading kb (K tile)
        #pragma unroll
        for (int j = 0; j < 4; j++) {          // pT[c][r] into kb
            int c = (tx << 2) + j;
            int sw = (c & 15) << 2;
            #pragma unroll
            for (int i = 0; i < 4; i++)
                kb[c][((ty << 2) + i) ^ sw] = s4[i][j];
        }
        __syncthreads();

        // O += P @ V
        #pragma unroll 8
        for (int c = 0; c < 64; c++) {
            int sw = (c & 15) << 2;
            float4 a  = *(const float4*)&kb[c][(ty << 2) ^ sw];
            float4 bv = *(const float4*)&vs[c][tx << 2];
            float av[4] = {a.x, a.y, a.z, a.w};
            float bb[4] = {bv.x, bv.y, bv.z, bv.w};
            #pragma unroll
            for (int i = 0; i < 4; i++)
                #pragma unroll
                for (int j = 0; j < 4; j++)
                    acc[i][j] = fmaf(av[i], bb[j], acc[i][j]);
        }
    }

    float invl[4];
    #pragma unroll
    for (int i = 0; i < 4; i++) invl[i] = 1.f / l_[i];

    __syncthreads();
    #pragma unroll
    for (int j = 0; j < 4; j++) {              // outT[d][r] into kb
        int d = (tx << 2) + j;
        int sw = (d & 15) << 2;
        #pragma unroll
        for (int i = 0; i < 4; i++)
            kb[d][((ty << 2) + i) ^ sw] = acc[i][j] * invl[i];
    }
    __syncthreads();

    // scramble: attention index bh -> (head' = bh/16, b' = bh%16)
    int bp  = bh & 15;
    int ch0 = (bh >> 4) << 6;
    float* op = g_attn + (size_t)(bp * Cc + ch0) * HWn + q0;
    #pragma unroll
    for (int it = 0; it < 16; it++) {
        int lin = tid + it * 256;
        int d = lin >> 6, r = lin & 63;
        op[(size_t)d * HWn + r] = kb[d][r ^ ((d & 15) << 2)];
    }
}

// ---------------------------------------------------------------------------
// Kernel 4: out = W_proj @ attn + bias + x. Tile 64(o) x 64(s) x 16(k).
// ---------------------------------------------------------------------------
__global__ __launch_bounds__(256) void proj_kernel(const float* __restrict__ W,
                                                   const float* __restrict__ bias,
                                                   const float* __restrict__ x,
                                                   float* __restrict__ out) {
    int b  = blockIdx.z;
    int o0 = blockIdx.y << 6;
    int n0 = blockIdx.x << 6;
    const float* sb = g_attn + (size_t)b * Cc * HWn;

    __shared__ float As[16][64];   // W tile [k][m] swizzled
    __shared__ float Bs[16][64];   // attn tile [k][n] natural

    int tid = threadIdx.x;
    int ty = tid >> 4, tx = tid & 15;
    int mrow = tid >> 2, kq = tid & 3;

    float acc[4][4];
    #pragma unroll
    for (int i = 0; i < 4; i++)
        #pragma unroll
        for (int j = 0; j < 4; j++) acc[i][j] = 0.f;

    for (int k0 = 0; k0 < Cc; k0 += 16) {
        {
            float4 w4 = *(const float4*)&W[(size_t)(o0 + mrow) * Cc + k0 + (kq << 2)];
            #pragma unroll
            for (int u = 0; u < 4; u++) {
                int k = (kq << 2) + u;
                As[k][mrow ^ (k << 2)] = (&w4.x)[u];
            }
        }
        #pragma unroll
        for (int it = 0; it < 4; it++) {
            int lin = tid + it * 256;
            int n = lin & 63, k = lin >> 6;
            Bs[k][n] = sb[(size_t)(k0 + k) * HWn + n0 + n];
        }
        __syncthreads();
        #pragma unroll
        for (int k = 0; k < 16; k++) {
            float4 a  = *(const float4*)&As[k][(ty << 2) ^ (k << 2)];
            float4 bv = *(const float4*)&Bs[k][tx << 2];
            float av[4] = {a.x, a.y, a.z, a.w};
            float bb[4] = {bv.x, bv.y, bv.z, bv.w};
            #pragma unroll
            for (int i = 0; i < 4; i++)
                #pragma unroll
                for (int j = 0; j < 4; j++)
                    acc[i][j] = fmaf(av[i], bb[j], acc[i][j]);
        }
        __syncthreads();
    }

    #pragma unroll
    for (int i = 0; i < 4; i++) {
        int o = o0 + (ty << 2) + i;
        float bval = bias[o];
        size_t off = (size_t)(b * Cc + o) * HWn + n0 + (tx << 2);
        float4 xv = *(const float4*)&x[off];
        float4 o4;
        o4.x = acc[i][0] + bval + xv.x;
        o4.y = acc[i][1] + bval + xv.y;
        o4.z = acc[i][2] + bval + xv.z;
        o4.w = acc[i][3] + bval + xv.w;
        *(float4*)&out[off] = o4;
    }
}

// ---------------------------------------------------------------------------
extern "C" void kernel_launch(void* const* d_in, const int* in_sizes, int n_in,
                              void* d_out, int out_size) {
    const float* x      = (const float*)d_in[0];
    const float* gamma  = (const float*)d_in[1];
    const float* beta   = (const float*)d_in[2];
    const float* w_qkv  = (const float*)d_in[3];
    const float* b_qkv  = (const float*)d_in[4];
    const float* w_proj = (const float*)d_in[5];
    const float* b_proj = (const float*)d_in[6];
    float* out = (float*)d_out;

    gn_kernel<<<Bn * 32, 256>>>(x, gamma, beta);
    qkv_gemm_kernel<<<dim3(HWn / 64, 3 * Cc / 64, Bn), 256>>>(w_qkv, b_qkv);
    attn_kernel<<<dim3(HWn / 64, Bn * NH), 256>>>();
    proj_kernel<<<dim3(HWn / 64, Cc / 64, Bn), 256>>>(w_proj, b_proj, x, out);
}

// round 3
// speedup vs baseline: 1.4572x; 1.4572x over previous
#include <cuda_runtime.h>
#include <cstdint>

#define Bn   16
#define Cc   512
#define HWn  1024
#define NH   8
#define DH   64

// Scratch (static device arrays — no cudaMalloc)
__device__ float g_ht[Bn * HWn * Cc];                // h^T  [b][hw][c]      (33.5 MB)
__device__ float g_qkv[Bn * NH * 3 * HWn * DH];      // [bh][part][s][c]    (100.7 MB)
__device__ float g_attn[Bn * HWn * Cc];              // attn out [b][s][c]  (33.5 MB)

// ---------------------------------------------------------------------------
// mma.sync tf32 helpers (sm_80-era PTX — compiles for plain sm_103 target)
// ---------------------------------------------------------------------------
__device__ __forceinline__ uint32_t f2tf(float x) {
    uint32_t r;
    asm("cvt.rna.tf32.f32 %0, %1;" : "=r"(r) : "f"(x));
    return r;
}

#define MMA_TF32(c, a, bfr)                                                   \
    asm volatile(                                                             \
        "mma.sync.aligned.m16n8k8.row.col.f32.tf32.tf32.f32 "                 \
        "{%0,%1,%2,%3}, {%4,%5,%6,%7}, {%8,%9}, {%0,%1,%2,%3};"               \
        : "+f"((c)[0]), "+f"((c)[1]), "+f"((c)[2]), "+f"((c)[3])              \
        : "r"((a)[0]), "r"((a)[1]), "r"((a)[2]), "r"((a)[3]),                 \
          "r"((bfr)[0]), "r"((bfr)[1]))

// ---------------------------------------------------------------------------
// Shared warp-MMA mainloop: D[128 x 128] = A[128 x 512] * B[128 x 512]^T
// 8 warps (2 m x 4 n), warp tile 64 x 32, k-tile 32, tf32 HMMA.
// acc[mi][ni][4]: mi -> 16-row tile within warp's 64 rows, ni -> 8-col tile.
// Fragment rows: g = lane>>2 (+8), cols: 2*tig, 2*tig+1 (tig = lane&3).
// ---------------------------------------------------------------------------
struct SmemTiles { uint32_t A[128][36]; uint32_t B[128][36]; };

__device__ __forceinline__ void gemm_mainloop(SmemTiles& sm,
                                              const float* __restrict__ Arow,
                                              const float* __restrict__ Brow,
                                              float acc[4][4][4]) {
    const int tid = threadIdx.x;
    const int warp = tid >> 5, lane = tid & 31;
    const int wm = warp & 1, wn = warp >> 1;
    const int g = lane >> 2, tig = lane & 3;

    #pragma unroll
    for (int mi = 0; mi < 4; mi++)
        #pragma unroll
        for (int ni = 0; ni < 4; ni++)
            #pragma unroll
            for (int c = 0; c < 4; c++) acc[mi][ni][c] = 0.f;

    #pragma unroll 1
    for (int k0 = 0; k0 < Cc; k0 += 32) {
        #pragma unroll
        for (int i = 0; i < 4; i++) {
            int lin = tid + i * 256;
            int r = lin >> 3, q = lin & 7;
            float4 va = *(const float4*)(Arow + (size_t)r * Cc + k0 + q * 4);
            uint4 ua = make_uint4(f2tf(va.x), f2tf(va.y), f2tf(va.z), f2tf(va.w));
            *(uint4*)&sm.A[r][q * 4] = ua;
            float4 vb = *(const float4*)(Brow + (size_t)r * Cc + k0 + q * 4);
            uint4 ub = make_uint4(f2tf(vb.x), f2tf(vb.y), f2tf(vb.z), f2tf(vb.w));
            *(uint4*)&sm.B[r][q * 4] = ub;
        }
        __syncthreads();
        #pragma unroll
        for (int kk = 0; kk < 32; kk += 8) {
            uint32_t af[4][4], bf[4][2];
            #pragma unroll
            for (int mi = 0; mi < 4; mi++) {
                int r = wm * 64 + mi * 16 + g;
                af[mi][0] = sm.A[r][kk + tig];
                af[mi][1] = sm.A[r + 8][kk + tig];
                af[mi][2] = sm.A[r][kk + tig + 4];
                af[mi][3] = sm.A[r + 8][kk + tig + 4];
            }
            #pragma unroll
            for (int ni = 0; ni < 4; ni++) {
                int r = wn * 32 + ni * 8 + g;
                bf[ni][0] = sm.B[r][kk + tig];
                bf[ni][1] = sm.B[r][kk + tig + 4];
            }
            #pragma unroll
            for (int mi = 0; mi < 4; mi++)
                #pragma unroll
                for (int ni = 0; ni < 4; ni++)
                    MMA_TF32(acc[mi][ni], af[mi], bf[ni]);
        }
        __syncthreads();
    }
}

// ---------------------------------------------------------------------------
// Kernel 1: GroupNorm -> g_ht[b][hw][c] (transposed for K-major MMA operand).
// ---------------------------------------------------------------------------
__global__ __launch_bounds__(256) void gn_kernel(const float* __restrict__ x,
                                                 const float* __restrict__ gamma,
                                                 const float* __restrict__ beta) {
    int b = blockIdx.x >> 5;
    int g = blockIdx.x & 31;
    int tid = threadIdx.x;
    size_t base = (size_t)(b * Cc + g * 16) * HWn;
    const float4* xp = (const float4*)(x + base);
    const int N4 = 16 * HWn / 4;   // 4096

    float s = 0.f, ss = 0.f;
    for (int i = tid; i < N4; i += 256) {
        float4 v = xp[i];
        s  += v.x + v.y + v.z + v.w;
        ss += v.x * v.x + v.y * v.y + v.z * v.z + v.w * v.w;
    }
    __shared__ float rs_[8], rss_[8];
    __shared__ float ga_s[16], be_s[16];
    __shared__ float tile[16][68];
    #pragma unroll
    for (int o = 16; o; o >>= 1) {
        s  += __shfl_xor_sync(0xffffffffu, s, o);
        ss += __shfl_xor_sync(0xffffffffu, ss, o);
    }
    int wid = tid >> 5, lid = tid & 31;
    if (lid == 0) { rs_[wid] = s; rss_[wid] = ss; }
    __syncthreads();
    if (tid < 32) {
        s = rs_[lid & 7]; ss = rss_[lid & 7];
        #pragma unroll
        for (int o = 4; o; o >>= 1) {
            s  += __shfl_xor_sync(0xffffffffu, s, o);
            ss += __shfl_xor_sync(0xffffffffu, ss, o);
        }
        if (lid == 0) { rs_[0] = s; rss_[0] = ss; }
    }
    __syncthreads();
    float mean = rs_[0] * (1.f / 16384.f);
    float var  = rss_[0] * (1.f / 16384.f) - mean * mean;
    float inv  = rsqrtf(var + 1e-5f);
    if (tid < 16) {
        float ga = gamma[g * 16 + tid] * inv;
        ga_s[tid] = ga;
        be_s[tid] = beta[g * 16 + tid] - mean * ga;
    }
    __syncthreads();

    float* outb = g_ht + (size_t)b * HWn * Cc + g * 16;
    int c = tid >> 4, q = tid & 15;       // load role
    int hw = tid >> 2, cq = tid & 3;      // store role
    for (int hw0 = 0; hw0 < HWn; hw0 += 64) {
        float4 v = xp[c * 256 + (hw0 >> 2) + q];
        float ga = ga_s[c], be = be_s[c];
        float4 o4;
        o4.x = v.x * ga + be; o4.y = v.y * ga + be;
        o4.z = v.z * ga + be; o4.w = v.w * ga + be;
        *(float4*)&tile[c][q << 2] = o4;
        __syncthreads();
        float4 w4;
        w4.x = tile[4 * cq + 0][hw];
        w4.y = tile[4 * cq + 1][hw];
        w4.z = tile[4 * cq + 2][hw];
        w4.w = tile[4 * cq + 3][hw];
        *(float4*)(outb + (size_t)(hw0 + hw) * Cc + 4 * cq) = w4;
        __syncthreads();
    }
}

// ---------------------------------------------------------------------------
// Kernel 2: qkv = W_qkv @ h  (tf32 HMMA). A = W rows (o), B = h^T rows (hw).
// Epilogue scatters to g_qkv[bh][part][s][c].
// ---------------------------------------------------------------------------
__global__ __launch_bounds__(256) void qkv_mma_kernel(const float* __restrict__ W,
                                                      const float* __restrict__ bias) {
    __shared__ SmemTiles sm;
    int b = blockIdx.z, o0 = blockIdx.x * 128, n0 = blockIdx.y * 128;
    const float* Arow = W + (size_t)o0 * Cc;
    const float* Brow = g_ht + ((size_t)b * HWn + n0) * Cc;
    float acc[4][4][4];
    gemm_mainloop(sm, Arow, Brow, acc);

    const int warp = threadIdx.x >> 5, lane = threadIdx.x & 31;
    const int wm = warp & 1, wn = warp >> 1;
    const int g = lane >> 2, tig = lane & 3;
    #pragma unroll
    for (int mi = 0; mi < 4; mi++) {
        #pragma unroll
        for (int h = 0; h < 2; h++) {
            int o = o0 + wm * 64 + mi * 16 + g + h * 8;
            int head = o / 192, rem = o - head * 192;
            int part = rem >> 6, c = rem & 63;
            float bv = __ldg(bias + o);
            float* dst = g_qkv + (size_t)((b * NH + head) * 3 + part) * HWn * DH + c;
            #pragma unroll
            for (int ni = 0; ni < 4; ni++) {
                int s = n0 + wn * 32 + ni * 8 + 2 * tig;
                dst[(size_t)s * DH]       = acc[mi][ni][h * 2 + 0] + bv;
                dst[(size_t)(s + 1) * DH] = acc[mi][ni][h * 2 + 1] + bv;
            }
        }
    }
}

// ---------------------------------------------------------------------------
// Kernel 3: flash attention (fp32). Epilogue -> g_attn[b][s][c].
// ---------------------------------------------------------------------------
__global__ __launch_bounds__(256) void attn_kernel() {
    int bh = blockIdx.y;
    int q0 = blockIdx.x << 6;
    int tid = threadIdx.x;
    int ty = tid >> 4, tx = tid & 15;

    __shared__ float qT[64][64];
    __shared__ float kb[64][64];
    __shared__ float vs[64][64];

    const float* qp = g_qkv + ((size_t)bh * 3 * HWn + q0) * DH;
    const float* kp = g_qkv + (size_t)(bh * 3 + 1) * HWn * DH;
    const float* vp = g_qkv + (size_t)(bh * 3 + 2) * HWn * DH;
    const float scale = 0.044194173824159216f;   // 512^-0.5

    #pragma unroll
    for (int it = 0; it < 4; it++) {
        int lin = tid + it * 256;
        int r = lin >> 4, dq = lin & 15;
        float4 v4 = *(const float4*)&qp[r * DH + (dq << 2)];
        #pragma unroll
        for (int u = 0; u < 4; u++) {
            int d = (dq << 2) + u;
            qT[d][r ^ ((d & 15) << 2)] = (&v4.x)[u];
        }
    }

    float m_[4], l_[4], acc[4][4];
    #pragma unroll
    for (int i = 0; i < 4; i++) {
        m_[i] = -1e30f; l_[i] = 0.f;
        #pragma unroll
        for (int j = 0; j < 4; j++) acc[i][j] = 0.f;
    }

    for (int t = 0; t < 16; t++) {
        __syncthreads();
        const float* kpt = kp + t * 64 * DH;
        const float* vpt = vp + t * 64 * DH;
        #pragma unroll
        for (int it = 0; it < 4; it++) {
            int lin = tid + it * 256;
            int c = lin >> 4, dq = lin & 15;
            float4 k4 = *(const float4*)&kpt[c * DH + (dq << 2)];
            #pragma unroll
            for (int u = 0; u < 4; u++) {
                int d = (dq << 2) + u;
                kb[d][c ^ ((d & 15) << 2)] = (&k4.x)[u] * scale;
            }
            float4 v4 = *(const float4*)&vpt[c * DH + (dq << 2)];
            *(float4*)&vs[c][dq << 2] = v4;
        }
        __syncthreads();

        float s4[4][4];
        #pragma unroll
        for (int i = 0; i < 4; i++)
            #pragma unroll
            for (int j = 0; j < 4; j++) s4[i][j] = 0.f;
        #pragma unroll 8
        for (int d = 0; d < 64; d++) {
            int sw = (d & 15) << 2;
            float4 a  = *(const float4*)&qT[d][(ty << 2) ^ sw];
            float4 bq = *(const float4*)&kb[d][(tx << 2) ^ sw];
            float av[4] = {a.x, a.y, a.z, a.w};
            float bb[4] = {bq.x, bq.y, bq.z, bq.w};
            #pragma unroll
            for (int i = 0; i < 4; i++)
                #pragma unroll
                for (int j = 0; j < 4; j++)
                    s4[i][j] = fmaf(av[i], bb[j], s4[i][j]);
        }

        #pragma unroll
        for (int i = 0; i < 4; i++) {
            float mx = fmaxf(fmaxf(s4[i][0], s4[i][1]), fmaxf(s4[i][2], s4[i][3]));
            mx = fmaxf(mx, __shfl_xor_sync(0xffffffffu, mx, 1));
            mx = fmaxf(mx, __shfl_xor_sync(0xffffffffu, mx, 2));
            mx = fmaxf(mx, __shfl_xor_sync(0xffffffffu, mx, 4));
            mx = fmaxf(mx, __shfl_xor_sync(0xffffffffu, mx, 8));
            float mn = fmaxf(m_[i], mx);
            float al = __expf(m_[i] - mn);
            float rs = 0.f;
            #pragma unroll
            for (int j = 0; j < 4; j++) { s4[i][j] = __expf(s4[i][j] - mn); rs += s4[i][j]; }
            rs += __shfl_xor_sync(0xffffffffu, rs, 1);
            rs += __shfl_xor_sync(0xffffffffu, rs, 2);
            rs += __shfl_xor_sync(0xffffffffu, rs, 4);
            rs += __shfl_xor_sync(0xffffffffu, rs, 8);
            l_[i] = l_[i] * al + rs;
            m_[i] = mn;
            #pragma unroll
            for (int j = 0; j < 4; j++) acc[i][j] *= al;
        }

        __syncthreads();
        #pragma unroll
        for (int j = 0; j < 4; j++) {
            int c = (tx << 2) + j;
            int sw = (c & 15) << 2;
            #pragma unroll
            for (int i = 0; i < 4; i++)
                kb[c][((ty << 2) + i) ^ sw] = s4[i][j];
        }
        __syncthreads();

        #pragma unroll 8
        for (int c = 0; c < 64; c++) {
            int sw = (c & 15) << 2;
            float4 a  = *(const float4*)&kb[c][(ty << 2) ^ sw];
            float4 bv = *(const float4*)&vs[c][tx << 2];
            float av[4] = {a.x, a.y, a.z, a.w};
            float bb[4] = {bv.x, bv.y, bv.z, bv.w};
            #pragma unroll
            for (int i = 0; i < 4; i++)
                #pragma unroll
                for (int j = 0; j < 4; j++)
                    acc[i][j] = fmaf(av[i], bb[j], acc[i][j]);
        }
    }

    float invl[4];
    #pragma unroll
    for (int i = 0; i < 4; i++) invl[i] = 1.f / l_[i];

    __syncthreads();
    // out[r][d] into kb, row-swizzled
    #pragma unroll
    for (int i = 0; i < 4; i++) {
        int r = (ty << 2) + i;
        int sw = (r & 15) << 2;
        float4 o4;
        o4.x = acc[i][0] * invl[i]; o4.y = acc[i][1] * invl[i];
        o4.z = acc[i][2] * invl[i]; o4.w = acc[i][3] * invl[i];
        *(float4*)&kb[r][(tx << 2) ^ sw] = o4;
    }
    __syncthreads();

    // head-major scramble: reference reads flat index bh as head'*16 + b'
    int bp  = bh & 15;
    int ch0 = (bh >> 4) << 6;
    float* op = g_attn + ((size_t)(bp * HWn) + q0) * Cc + ch0;
    #pragma unroll
    for (int it = 0; it < 16; it++) {
        int lin = tid + it * 256;
        int r = lin >> 6, d = lin & 63;
        op[(size_t)r * Cc + d] = kb[r][d ^ ((r & 15) << 2)];
    }
}

// ---------------------------------------------------------------------------
// Kernel 4: out = W_proj @ attn + bias + x (tf32 HMMA).
// A = W_proj rows (o), B = attn rows (s). float2 stores along hw.
// ---------------------------------------------------------------------------
__global__ __launch_bounds__(256) void proj_mma_kernel(const float* __restrict__ W,
                                                       const float* __restrict__ bias,
                                                       const float* __restrict__ x,
                                                       float* __restrict__ out) {
    __shared__ SmemTiles sm;
    int b = blockIdx.z, o0 = blockIdx.x * 128, n0 = blockIdx.y * 128;
    const float* Arow = W + (size_t)o0 * Cc;
    const float* Brow = g_attn + ((size_t)b * HWn + n0) * Cc;
    float acc[4][4][4];
    gemm_mainloop(sm, Arow, Brow, acc);

    const int warp = threadIdx.x >> 5, lane = threadIdx.x & 31;
    const int wm = warp & 1, wn = warp >> 1;
    const int g = lane >> 2, tig = lane & 3;
    #pragma unroll
    for (int mi = 0; mi < 4; mi++) {
        #pragma unroll
        for (int h = 0; h < 2; h++) {
            int o = o0 + wm * 64 + mi * 16 + g + h * 8;
            float bv = __ldg(bias + o);
            size_t rowoff = (size_t)(b * Cc + o) * HWn;
            #pragma unroll
            for (int ni = 0; ni < 4; ni++) {
                int s = n0 + wn * 32 + ni * 8 + 2 * tig;
                float2 xv = *(const float2*)&x[rowoff + s];
                float2 ov;
                ov.x = acc[mi][ni][h * 2 + 0] + bv + xv.x;
                ov.y = acc[mi][ni][h * 2 + 1] + bv + xv.y;
                *(float2*)&out[rowoff + s] = ov;
            }
        }
    }
}

// ---------------------------------------------------------------------------
extern "C" void kernel_launch(void* const* d_in, const int* in_sizes, int n_in,
                              void* d_out, int out_size) {
    const float* x      = (const float*)d_in[0];
    const float* gamma  = (const float*)d_in[1];
    const float* beta   = (const float*)d_in[2];
    const float* w_qkv  = (const float*)d_in[3];
    const float* b_qkv  = (const float*)d_in[4];
    const float* w_proj = (const float*)d_in[5];
    const float* b_proj = (const float*)d_in[6];
    float* out = (float*)d_out;

    gn_kernel<<<Bn * 32, 256>>>(x, gamma, beta);
    qkv_mma_kernel<<<dim3(12, 8, Bn), 256>>>(w_qkv, b_qkv);
    attn_kernel<<<dim3(HWn / 64, Bn * NH), 256>>>();
    proj_mma_kernel<<<dim3(4, 8, Bn), 256>>>(w_proj, b_proj, x, out);
}

// round 4
// speedup vs baseline: 2.6634x; 1.8278x over previous
#include <cuda_runtime.h>
#include <cstdint>

#define Bn   16
#define Cc   512
#define HWn  1024
#define NH   8
#define DH   64

// Scratch (static device arrays — no cudaMalloc)
__device__ float g_ht[Bn * HWn * Cc];                // h^T  [b][hw][c]      (33.5 MB)
__device__ float g_qkv[Bn * NH * 3 * HWn * DH];      // [bh][part][s][c]    (100.7 MB)
__device__ float g_attn[Bn * HWn * Cc];              // attn out [b][s][c]  (33.5 MB)

// ---------------------------------------------------------------------------
// mma.sync tf32 helpers (sm_80-era PTX — compiles for plain sm_103 target)
// ---------------------------------------------------------------------------
__device__ __forceinline__ uint32_t f2tf(float x) {
    uint32_t r;
    asm("cvt.rna.tf32.f32 %0, %1;" : "=r"(r) : "f"(x));
    return r;
}

#define MMA_TF32(c, a, bfr)                                                   \
    asm volatile(                                                             \
        "mma.sync.aligned.m16n8k8.row.col.f32.tf32.tf32.f32 "                 \
        "{%0,%1,%2,%3}, {%4,%5,%6,%7}, {%8,%9}, {%0,%1,%2,%3};"               \
        : "+f"((c)[0]), "+f"((c)[1]), "+f"((c)[2]), "+f"((c)[3])              \
        : "r"((a)[0]), "r"((a)[1]), "r"((a)[2]), "r"((a)[3]),                 \
          "r"((bfr)[0]), "r"((bfr)[1]))

// ---------------------------------------------------------------------------
// Shared warp-MMA GEMM mainloop: D[128 x 128] = A[128 x 512] * B[128 x 512]^T
// 8 warps (2 m x 4 n), warp tile 64 x 32, k-tile 32, tf32 HMMA.
// ---------------------------------------------------------------------------
struct SmemTiles { uint32_t A[128][36]; uint32_t B[128][36]; };

__device__ __forceinline__ void gemm_mainloop(SmemTiles& sm,
                                              const float* __restrict__ Arow,
                                              const float* __restrict__ Brow,
                                              float acc[4][4][4]) {
    const int tid = threadIdx.x;
    const int warp = tid >> 5, lane = tid & 31;
    const int wm = warp & 1, wn = warp >> 1;
    const int g = lane >> 2, tig = lane & 3;

    #pragma unroll
    for (int mi = 0; mi < 4; mi++)
        #pragma unroll
        for (int ni = 0; ni < 4; ni++)
            #pragma unroll
            for (int c = 0; c < 4; c++) acc[mi][ni][c] = 0.f;

    #pragma unroll 1
    for (int k0 = 0; k0 < Cc; k0 += 32) {
        #pragma unroll
        for (int i = 0; i < 4; i++) {
            int lin = tid + i * 256;
            int r = lin >> 3, q = lin & 7;
            float4 va = *(const float4*)(Arow + (size_t)r * Cc + k0 + q * 4);
            uint4 ua = make_uint4(f2tf(va.x), f2tf(va.y), f2tf(va.z), f2tf(va.w));
            *(uint4*)&sm.A[r][q * 4] = ua;
            float4 vb = *(const float4*)(Brow + (size_t)r * Cc + k0 + q * 4);
            uint4 ub = make_uint4(f2tf(vb.x), f2tf(vb.y), f2tf(vb.z), f2tf(vb.w));
            *(uint4*)&sm.B[r][q * 4] = ub;
        }
        __syncthreads();
        #pragma unroll
        for (int kk = 0; kk < 32; kk += 8) {
            uint32_t af[4][4], bf[4][2];
            #pragma unroll
            for (int mi = 0; mi < 4; mi++) {
                int r = wm * 64 + mi * 16 + g;
                af[mi][0] = sm.A[r][kk + tig];
                af[mi][1] = sm.A[r + 8][kk + tig];
                af[mi][2] = sm.A[r][kk + tig + 4];
                af[mi][3] = sm.A[r + 8][kk + tig + 4];
            }
            #pragma unroll
            for (int ni = 0; ni < 4; ni++) {
                int r = wn * 32 + ni * 8 + g;
                bf[ni][0] = sm.B[r][kk + tig];
                bf[ni][1] = sm.B[r][kk + tig + 4];
            }
            #pragma unroll
            for (int mi = 0; mi < 4; mi++)
                #pragma unroll
                for (int ni = 0; ni < 4; ni++)
                    MMA_TF32(acc[mi][ni], af[mi], bf[ni]);
        }
        __syncthreads();
    }
}

// ---------------------------------------------------------------------------
// Kernel 1: GroupNorm -> g_ht[b][hw][c] (transposed for K-major MMA operand).
// ---------------------------------------------------------------------------
__global__ __launch_bounds__(256) void gn_kernel(const float* __restrict__ x,
                                                 const float* __restrict__ gamma,
                                                 const float* __restrict__ beta) {
    int b = blockIdx.x >> 5;
    int g = blockIdx.x & 31;
    int tid = threadIdx.x;
    size_t base = (size_t)(b * Cc + g * 16) * HWn;
    const float4* xp = (const float4*)(x + base);
    const int N4 = 16 * HWn / 4;   // 4096

    float s = 0.f, ss = 0.f;
    for (int i = tid; i < N4; i += 256) {
        float4 v = xp[i];
        s  += v.x + v.y + v.z + v.w;
        ss += v.x * v.x + v.y * v.y + v.z * v.z + v.w * v.w;
    }
    __shared__ float rs_[8], rss_[8];
    __shared__ float ga_s[16], be_s[16];
    __shared__ float tile[16][68];
    #pragma unroll
    for (int o = 16; o; o >>= 1) {
        s  += __shfl_xor_sync(0xffffffffu, s, o);
        ss += __shfl_xor_sync(0xffffffffu, ss, o);
    }
    int wid = tid >> 5, lid = tid & 31;
    if (lid == 0) { rs_[wid] = s; rss_[wid] = ss; }
    __syncthreads();
    if (tid < 32) {
        s = rs_[lid & 7]; ss = rss_[lid & 7];
        #pragma unroll
        for (int o = 4; o; o >>= 1) {
            s  += __shfl_xor_sync(0xffffffffu, s, o);
            ss += __shfl_xor_sync(0xffffffffu, ss, o);
        }
        if (lid == 0) { rs_[0] = s; rss_[0] = ss; }
    }
    __syncthreads();
    float mean = rs_[0] * (1.f / 16384.f);
    float var  = rss_[0] * (1.f / 16384.f) - mean * mean;
    float inv  = rsqrtf(var + 1e-5f);
    if (tid < 16) {
        float ga = gamma[g * 16 + tid] * inv;
        ga_s[tid] = ga;
        be_s[tid] = beta[g * 16 + tid] - mean * ga;
    }
    __syncthreads();

    float* outb = g_ht + (size_t)b * HWn * Cc + g * 16;
    int c = tid >> 4, q = tid & 15;       // load role
    int hw = tid >> 2, cq = tid & 3;      // store role
    for (int hw0 = 0; hw0 < HWn; hw0 += 64) {
        float4 v = xp[c * 256 + (hw0 >> 2) + q];
        float ga = ga_s[c], be = be_s[c];
        float4 o4;
        o4.x = v.x * ga + be; o4.y = v.y * ga + be;
        o4.z = v.z * ga + be; o4.w = v.w * ga + be;
        *(float4*)&tile[c][q << 2] = o4;
        __syncthreads();
        float4 w4;
        w4.x = tile[4 * cq + 0][hw];
        w4.y = tile[4 * cq + 1][hw];
        w4.z = tile[4 * cq + 2][hw];
        w4.w = tile[4 * cq + 3][hw];
        *(float4*)(outb + (size_t)(hw0 + hw) * Cc + 4 * cq) = w4;
        __syncthreads();
    }
}

// ---------------------------------------------------------------------------
// Kernel 2: qkv = W_qkv @ h  (tf32 HMMA). Scatters to g_qkv[bh][part][s][c].
// ---------------------------------------------------------------------------
__global__ __launch_bounds__(256) void qkv_mma_kernel(const float* __restrict__ W,
                                                      const float* __restrict__ bias) {
    __shared__ SmemTiles sm;
    int b = blockIdx.z, o0 = blockIdx.x * 128, n0 = blockIdx.y * 128;
    const float* Arow = W + (size_t)o0 * Cc;
    const float* Brow = g_ht + ((size_t)b * HWn + n0) * Cc;
    float acc[4][4][4];
    gemm_mainloop(sm, Arow, Brow, acc);

    const int warp = threadIdx.x >> 5, lane = threadIdx.x & 31;
    const int wm = warp & 1, wn = warp >> 1;
    const int g = lane >> 2, tig = lane & 3;
    #pragma unroll
    for (int mi = 0; mi < 4; mi++) {
        #pragma unroll
        for (int h = 0; h < 2; h++) {
            int o = o0 + wm * 64 + mi * 16 + g + h * 8;
            int head = o / 192, rem = o - head * 192;
            int part = rem >> 6, c = rem & 63;
            float bv = __ldg(bias + o);
            float* dst = g_qkv + (size_t)((b * NH + head) * 3 + part) * HWn * DH + c;
            #pragma unroll
            for (int ni = 0; ni < 4; ni++) {
                int s = n0 + wn * 32 + ni * 8 + 2 * tig;
                dst[(size_t)s * DH]       = acc[mi][ni][h * 2 + 0] + bv;
                dst[(size_t)(s + 1) * DH] = acc[mi][ni][h * 2 + 1] + bv;
            }
        }
    }
}

// ---------------------------------------------------------------------------
// Kernel 3: flash attention on tf32 HMMA.
// Block = (bh, 64-query tile), 4 warps; warp = 16-row m-tile.
// Smem (dynamic, 68608 B): Qs[64][68], Ks[64][68], Ps[64][68], Vt[64][64]^xor.
// ---------------------------------------------------------------------------
__global__ __launch_bounds__(128) void attn_mma_kernel() {
    extern __shared__ uint32_t smn[];
    uint32_t* Qs = smn;             // [64][68] tf32, scale folded in
    uint32_t* Ks = smn + 4352;      // [64][68] tf32, [key][dh]
    uint32_t* Ps = smn + 8704;      // [64][68] tf32, [q][key]
    uint32_t* Vt = smn + 13056;     // [64][64] tf32, [dh][key] xor-swizzled

    int bh = blockIdx.y;
    int q0 = blockIdx.x << 6;
    int tid = threadIdx.x;
    int w = tid >> 5, lane = tid & 31;
    int g = lane >> 2, tig = lane & 3;

    const float* qp = g_qkv + ((size_t)bh * 3 * HWn + q0) * DH;
    const float* kp = g_qkv + (size_t)(bh * 3 + 1) * HWn * DH;
    const float* vp = g_qkv + (size_t)(bh * 3 + 2) * HWn * DH;
    const float scale = 0.044194173824159216f;   // 512^-0.5, folded into Q

    #pragma unroll
    for (int it = 0; it < 8; it++) {
        int lin = tid + it * 128;
        int r = lin >> 4, dq = lin & 15;
        float4 v = *(const float4*)&qp[r * DH + dq * 4];
        Qs[r * 68 + dq * 4 + 0] = f2tf(v.x * scale);
        Qs[r * 68 + dq * 4 + 1] = f2tf(v.y * scale);
        Qs[r * 68 + dq * 4 + 2] = f2tf(v.z * scale);
        Qs[r * 68 + dq * 4 + 3] = f2tf(v.w * scale);
    }

    float oacc[8][4];
    #pragma unroll
    for (int nd = 0; nd < 8; nd++)
        #pragma unroll
        for (int c = 0; c < 4; c++) oacc[nd][c] = 0.f;
    float m0 = -1e30f, m1 = -1e30f, l0 = 0.f, l1 = 0.f;

    const int row = w * 16 + g;

    #pragma unroll 1
    for (int t = 0; t < 16; t++) {
        __syncthreads();                       // prev tile's Ks/Vt reads done
        const float* kpt = kp + (size_t)t * 64 * DH;
        const float* vpt = vp + (size_t)t * 64 * DH;
        #pragma unroll
        for (int it = 0; it < 8; it++) {
            int lin = tid + it * 128;
            int r = lin >> 4, dq = lin & 15;
            float4 kv = *(const float4*)&kpt[r * DH + dq * 4];
            Ks[r * 68 + dq * 4 + 0] = f2tf(kv.x);
            Ks[r * 68 + dq * 4 + 1] = f2tf(kv.y);
            Ks[r * 68 + dq * 4 + 2] = f2tf(kv.z);
            Ks[r * 68 + dq * 4 + 3] = f2tf(kv.w);
            float4 vv = *(const float4*)&vpt[r * DH + dq * 4];
            #pragma unroll
            for (int u = 0; u < 4; u++) {
                int d = dq * 4 + u;
                Vt[d * 64 + (r ^ ((d & 15) << 2))] = f2tf((&vv.x)[u]);
            }
        }
        __syncthreads();

        // ---- S = Q @ K^T (64 x 64 per block, 16 x 64 per warp) ----
        float sacc[8][4];
        #pragma unroll
        for (int ni = 0; ni < 8; ni++)
            #pragma unroll
            for (int c = 0; c < 4; c++) sacc[ni][c] = 0.f;
        #pragma unroll
        for (int kk = 0; kk < 8; kk++) {
            uint32_t af[4];
            af[0] = Qs[row * 68 + kk * 8 + tig];
            af[1] = Qs[(row + 8) * 68 + kk * 8 + tig];
            af[2] = Qs[row * 68 + kk * 8 + tig + 4];
            af[3] = Qs[(row + 8) * 68 + kk * 8 + tig + 4];
            #pragma unroll
            for (int ni = 0; ni < 8; ni++) {
                uint32_t bf[2];
                bf[0] = Ks[(ni * 8 + g) * 68 + kk * 8 + tig];
                bf[1] = Ks[(ni * 8 + g) * 68 + kk * 8 + tig + 4];
                MMA_TF32(sacc[ni], af, bf);
            }
        }

        // ---- online softmax (rows g, g+8; quad = lanes sharing g) ----
        float mx0 = -1e30f, mx1 = -1e30f;
        #pragma unroll
        for (int ni = 0; ni < 8; ni++) {
            mx0 = fmaxf(mx0, fmaxf(sacc[ni][0], sacc[ni][1]));
            mx1 = fmaxf(mx1, fmaxf(sacc[ni][2], sacc[ni][3]));
        }
        mx0 = fmaxf(mx0, __shfl_xor_sync(0xffffffffu, mx0, 1));
        mx0 = fmaxf(mx0, __shfl_xor_sync(0xffffffffu, mx0, 2));
        mx1 = fmaxf(mx1, __shfl_xor_sync(0xffffffffu, mx1, 1));
        mx1 = fmaxf(mx1, __shfl_xor_sync(0xffffffffu, mx1, 2));
        float mn0 = fmaxf(m0, mx0), mn1 = fmaxf(m1, mx1);
        float al0 = __expf(m0 - mn0), al1 = __expf(m1 - mn1);
        float rs0 = 0.f, rs1 = 0.f;
        #pragma unroll
        for (int ni = 0; ni < 8; ni++) {
            sacc[ni][0] = __expf(sacc[ni][0] - mn0); rs0 += sacc[ni][0];
            sacc[ni][1] = __expf(sacc[ni][1] - mn0); rs0 += sacc[ni][1];
            sacc[ni][2] = __expf(sacc[ni][2] - mn1); rs1 += sacc[ni][2];
            sacc[ni][3] = __expf(sacc[ni][3] - mn1); rs1 += sacc[ni][3];
        }
        rs0 += __shfl_xor_sync(0xffffffffu, rs0, 1);
        rs0 += __shfl_xor_sync(0xffffffffu, rs0, 2);
        rs1 += __shfl_xor_sync(0xffffffffu, rs1, 1);
        rs1 += __shfl_xor_sync(0xffffffffu, rs1, 2);
        l0 = l0 * al0 + rs0; m0 = mn0;
        l1 = l1 * al1 + rs1; m1 = mn1;
        #pragma unroll
        for (int nd = 0; nd < 8; nd++) {
            oacc[nd][0] *= al0; oacc[nd][1] *= al0;
            oacc[nd][2] *= al1; oacc[nd][3] *= al1;
        }

        // ---- P -> smem (per-warp rows only) ----
        #pragma unroll
        for (int ni = 0; ni < 8; ni++) {
            Ps[row * 68 + ni * 8 + 2 * tig]           = f2tf(sacc[ni][0]);
            Ps[row * 68 + ni * 8 + 2 * tig + 1]       = f2tf(sacc[ni][1]);
            Ps[(row + 8) * 68 + ni * 8 + 2 * tig]     = f2tf(sacc[ni][2]);
            Ps[(row + 8) * 68 + ni * 8 + 2 * tig + 1] = f2tf(sacc[ni][3]);
        }
        __syncwarp();

        // ---- O += P @ V ----
        #pragma unroll
        for (int kk = 0; kk < 8; kk++) {
            uint32_t af[4];
            af[0] = Ps[row * 68 + kk * 8 + tig];
            af[1] = Ps[(row + 8) * 68 + kk * 8 + tig];
            af[2] = Ps[row * 68 + kk * 8 + tig + 4];
            af[3] = Ps[(row + 8) * 68 + kk * 8 + tig + 4];
            #pragma unroll
            for (int nd = 0; nd < 8; nd++) {
                int dn = nd * 8 + g;
                int swz = (dn & 15) << 2;
                uint32_t bf[2];
                bf[0] = Vt[dn * 64 + ((kk * 8 + tig) ^ swz)];
                bf[1] = Vt[dn * 64 + ((kk * 8 + tig + 4) ^ swz)];
                MMA_TF32(oacc[nd], af, bf);
            }
        }
    }

    // ---- epilogue: divide by l, head-major scramble, float2 stores ----
    float il0 = 1.f / l0, il1 = 1.f / l1;
    int bp  = bh & 15;
    int ch0 = (bh >> 4) << 6;
    int s0 = q0 + row;
    #pragma unroll
    for (int nd = 0; nd < 8; nd++) {
        int c = ch0 + nd * 8 + 2 * tig;
        float2 v0, v1;
        v0.x = oacc[nd][0] * il0; v0.y = oacc[nd][1] * il0;
        v1.x = oacc[nd][2] * il1; v1.y = oacc[nd][3] * il1;
        *(float2*)(g_attn + ((size_t)(bp * HWn + s0)) * Cc + c)     = v0;
        *(float2*)(g_attn + ((size_t)(bp * HWn + s0 + 8)) * Cc + c) = v1;
    }
}

// ---------------------------------------------------------------------------
// Kernel 4: out = W_proj @ attn + bias + x (tf32 HMMA).
// ---------------------------------------------------------------------------
__global__ __launch_bounds__(256) void proj_mma_kernel(const float* __restrict__ W,
                                                       const float* __restrict__ bias,
                                                       const float* __restrict__ x,
                                                       float* __restrict__ out) {
    __shared__ SmemTiles sm;
    int b = blockIdx.z, o0 = blockIdx.x * 128, n0 = blockIdx.y * 128;
    const float* Arow = W + (size_t)o0 * Cc;
    const float* Brow = g_attn + ((size_t)b * HWn + n0) * Cc;
    float acc[4][4][4];
    gemm_mainloop(sm, Arow, Brow, acc);

    const int warp = threadIdx.x >> 5, lane = threadIdx.x & 31;
    const int wm = warp & 1, wn = warp >> 1;
    const int g = lane >> 2, tig = lane & 3;
    #pragma unroll
    for (int mi = 0; mi < 4; mi++) {
        #pragma unroll
        for (int h = 0; h < 2; h++) {
            int o = o0 + wm * 64 + mi * 16 + g + h * 8;
            float bv = __ldg(bias + o);
            size_t rowoff = (size_t)(b * Cc + o) * HWn;
            #pragma unroll
            for (int ni = 0; ni < 4; ni++) {
                int s = n0 + wn * 32 + ni * 8 + 2 * tig;
                float2 xv = *(const float2*)&x[rowoff + s];
                float2 ov;
                ov.x = acc[mi][ni][h * 2 + 0] + bv + xv.x;
                ov.y = acc[mi][ni][h * 2 + 1] + bv + xv.y;
                *(float2*)&out[rowoff + s] = ov;
            }
        }
    }
}

// ---------------------------------------------------------------------------
extern "C" void kernel_launch(void* const* d_in, const int* in_sizes, int n_in,
                              void* d_out, int out_size) {
    const float* x      = (const float*)d_in[0];
    const float* gamma  = (const float*)d_in[1];
    const float* beta   = (const float*)d_in[2];
    const float* w_qkv  = (const float*)d_in[3];
    const float* b_qkv  = (const float*)d_in[4];
    const float* w_proj = (const float*)d_in[5];
    const float* b_proj = (const float*)d_in[6];
    float* out = (float*)d_out;

    const int ATTN_SMEM = 68608;
    cudaFuncSetAttribute(attn_mma_kernel,
                         cudaFuncAttributeMaxDynamicSharedMemorySize, ATTN_SMEM);

    gn_kernel<<<Bn * 32, 256>>>(x, gamma, beta);
    qkv_mma_kernel<<<dim3(12, 8, Bn), 256>>>(w_qkv, b_qkv);
    attn_mma_kernel<<<dim3(HWn / 64, Bn * NH), 128, ATTN_SMEM>>>();
    proj_mma_kernel<<<dim3(4, 8, Bn), 256>>>(w_proj, b_proj, x, out);
}

// round 5
// speedup vs baseline: 3.2149x; 1.2071x over previous
#include <cuda_runtime.h>
#include <cstdint>

#define Bn   16
#define Cc   512
#define HWn  1024
#define NH   8
#define DH   64

// Scratch (static device arrays — no cudaMalloc)
__device__ float g_ht[Bn * HWn * Cc];                // h^T  [b][hw][c]
__device__ float g_qkv[Bn * NH * 3 * HWn * DH];      // q,k: [bh][p][s][c]; v: [bh][2][c][s]
__device__ float g_attn[Bn * HWn * Cc];              // attn out [b][s][c]

// ---------------------------------------------------------------------------
// PTX helpers (sm_80-era — compiles for plain sm_103 target)
// ---------------------------------------------------------------------------
__device__ __forceinline__ uint32_t smem_u32(const void* p) {
    uint32_t a;
    asm("{ .reg .u64 t; cvta.to.shared.u64 t, %1; cvt.u32.u64 %0, t; }" : "=r"(a) : "l"(p));
    return a;
}
#define CP16(dst, src)                                                        \
    asm volatile("cp.async.cg.shared.global [%0], [%1], 16;"                  \
                 :: "r"(dst), "l"(src))
#define CP_COMMIT() asm volatile("cp.async.commit_group;" ::: "memory")
#define CP_WAIT1()  asm volatile("cp.async.wait_group 1;" ::: "memory")
#define CP_WAIT0()  asm volatile("cp.async.wait_group 0;" ::: "memory")

// raw-f32 operands: tf32 HMMA truncates low mantissa bits in hardware
#define MMA_TF32(c, a, bfr)                                                   \
    asm volatile(                                                             \
        "mma.sync.aligned.m16n8k8.row.col.f32.tf32.tf32.f32 "                 \
        "{%0,%1,%2,%3}, {%4,%5,%6,%7}, {%8,%9}, {%0,%1,%2,%3};"               \
        : "+f"((c)[0]), "+f"((c)[1]), "+f"((c)[2]), "+f"((c)[3])              \
        : "r"((a)[0]), "r"((a)[1]), "r"((a)[2]), "r"((a)[3]),                 \
          "r"((bfr)[0]), "r"((bfr)[1]))

// ---------------------------------------------------------------------------
// Warp-MMA GEMM mainloop, cp.async 2-stage: D[128x128] = A[128x512]*B[128x512]^T
// 8 warps (2m x 4n), warp tile 64x32, k-tile 32. Dyn smem: 2 stages A+B,
// stride 36 (rows 144B, 16B-aligned; fragment banks 4g+tig conflict-free).
// ---------------------------------------------------------------------------
__device__ __forceinline__ void gemm_fill(uint32_t sb, int st,
                                          const float* __restrict__ Arow,
                                          const float* __restrict__ Brow,
                                          int k0, int tid) {
    #pragma unroll
    for (int i = 0; i < 4; i++) {
        int id = tid + i * 256;
        int r = id >> 3, q = id & 7;
        CP16(sb + (uint32_t)(st * 4608 + r * 36 + q * 4) * 4,
             Arow + (size_t)r * Cc + k0 + q * 4);
        CP16(sb + (uint32_t)(9216 + st * 4608 + r * 36 + q * 4) * 4,
             Brow + (size_t)r * Cc + k0 + q * 4);
    }
}

__device__ __forceinline__ void gemm_mainloop(const float* __restrict__ Arow,
                                              const float* __restrict__ Brow,
                                              float acc[4][4][4]) {
    extern __shared__ uint32_t gsm[];
    uint32_t sb = smem_u32(gsm);
    const uint32_t* Au = gsm;
    const uint32_t* Bu = gsm + 9216;
    const int tid = threadIdx.x;
    const int warp = tid >> 5, lane = tid & 31;
    const int wm = warp & 1, wn = warp >> 1;
    const int g = lane >> 2, tig = lane & 3;

    #pragma unroll
    for (int mi = 0; mi < 4; mi++)
        #pragma unroll
        for (int ni = 0; ni < 4; ni++)
            #pragma unroll
            for (int c = 0; c < 4; c++) acc[mi][ni][c] = 0.f;

    gemm_fill(sb, 0, Arow, Brow, 0, tid);
    CP_COMMIT();

    #pragma unroll 1
    for (int it = 0; it < 16; it++) {
        const int st = it & 1;
        if (it + 1 < 16) {
            gemm_fill(sb, st ^ 1, Arow, Brow, (it + 1) * 32, tid);
            CP_COMMIT();
            CP_WAIT1();
        } else {
            CP_WAIT0();
        }
        __syncthreads();
        const uint32_t* As = Au + st * 4608;
        const uint32_t* Bs = Bu + st * 4608;
        #pragma unroll
        for (int kk = 0; kk < 32; kk += 8) {
            uint32_t af[4][4], bf[4][2];
            #pragma unroll
            for (int mi = 0; mi < 4; mi++) {
                int r = wm * 64 + mi * 16 + g;
                af[mi][0] = As[r * 36 + kk + tig];
                af[mi][1] = As[(r + 8) * 36 + kk + tig];
                af[mi][2] = As[r * 36 + kk + tig + 4];
                af[mi][3] = As[(r + 8) * 36 + kk + tig + 4];
            }
            #pragma unroll
            for (int ni = 0; ni < 4; ni++) {
                int r = wn * 32 + ni * 8 + g;
                bf[ni][0] = Bs[r * 36 + kk + tig];
                bf[ni][1] = Bs[r * 36 + kk + tig + 4];
            }
            #pragma unroll
            for (int mi = 0; mi < 4; mi++)
                #pragma unroll
                for (int ni = 0; ni < 4; ni++)
                    MMA_TF32(acc[mi][ni], af[mi], bf[ni]);
        }
        __syncthreads();
    }
}

// ---------------------------------------------------------------------------
// Kernel 1: GroupNorm -> g_ht[b][hw][c].
// ---------------------------------------------------------------------------
__global__ __launch_bounds__(256) void gn_kernel(const float* __restrict__ x,
                                                 const float* __restrict__ gamma,
                                                 const float* __restrict__ beta) {
    int b = blockIdx.x >> 5;
    int g = blockIdx.x & 31;
    int tid = threadIdx.x;
    size_t base = (size_t)(b * Cc + g * 16) * HWn;
    const float4* xp = (const float4*)(x + base);
    const int N4 = 16 * HWn / 4;

    float s = 0.f, ss = 0.f;
    for (int i = tid; i < N4; i += 256) {
        float4 v = xp[i];
        s  += v.x + v.y + v.z + v.w;
        ss += v.x * v.x + v.y * v.y + v.z * v.z + v.w * v.w;
    }
    __shared__ float rs_[8], rss_[8];
    __shared__ float ga_s[16], be_s[16];
    __shared__ float tile[16][68];
    #pragma unroll
    for (int o = 16; o; o >>= 1) {
        s  += __shfl_xor_sync(0xffffffffu, s, o);
        ss += __shfl_xor_sync(0xffffffffu, ss, o);
    }
    int wid = tid >> 5, lid = tid & 31;
    if (lid == 0) { rs_[wid] = s; rss_[wid] = ss; }
    __syncthreads();
    if (tid < 32) {
        s = rs_[lid & 7]; ss = rss_[lid & 7];
        #pragma unroll
        for (int o = 4; o; o >>= 1) {
            s  += __shfl_xor_sync(0xffffffffu, s, o);
            ss += __shfl_xor_sync(0xffffffffu, ss, o);
        }
        if (lid == 0) { rs_[0] = s; rss_[0] = ss; }
    }
    __syncthreads();
    float mean = rs_[0] * (1.f / 16384.f);
    float var  = rss_[0] * (1.f / 16384.f) - mean * mean;
    float inv  = rsqrtf(var + 1e-5f);
    if (tid < 16) {
        float ga = gamma[g * 16 + tid] * inv;
        ga_s[tid] = ga;
        be_s[tid] = beta[g * 16 + tid] - mean * ga;
    }
    __syncthreads();

    float* outb = g_ht + (size_t)b * HWn * Cc + g * 16;
    int c = tid >> 4, q = tid & 15;
    int hw = tid >> 2, cq = tid & 3;
    for (int hw0 = 0; hw0 < HWn; hw0 += 64) {
        float4 v = xp[c * 256 + (hw0 >> 2) + q];
        float ga = ga_s[c], be = be_s[c];
        float4 o4;
        o4.x = v.x * ga + be; o4.y = v.y * ga + be;
        o4.z = v.z * ga + be; o4.w = v.w * ga + be;
        *(float4*)&tile[c][q << 2] = o4;
        __syncthreads();
        float4 w4;
        w4.x = tile[4 * cq + 0][hw];
        w4.y = tile[4 * cq + 1][hw];
        w4.z = tile[4 * cq + 2][hw];
        w4.w = tile[4 * cq + 3][hw];
        *(float4*)(outb + (size_t)(hw0 + hw) * Cc + 4 * cq) = w4;
        __syncthreads();
    }
}

// ---------------------------------------------------------------------------
// Kernel 2: qkv GEMM. q,k parts -> [s][c]; v part -> TRANSPOSED [c][s].
// ---------------------------------------------------------------------------
__global__ __launch_bounds__(256) void qkv_mma_kernel(const float* __restrict__ W,
                                                      const float* __restrict__ bias) {
    int b = blockIdx.z, o0 = blockIdx.x * 128, n0 = blockIdx.y * 128;
    const float* Arow = W + (size_t)o0 * Cc;
    const float* Brow = g_ht + ((size_t)b * HWn + n0) * Cc;
    float acc[4][4][4];
    gemm_mainloop(Arow, Brow, acc);

    const int warp = threadIdx.x >> 5, lane = threadIdx.x & 31;
    const int wm = warp & 1, wn = warp >> 1;
    const int g = lane >> 2, tig = lane & 3;
    #pragma unroll
    for (int mi = 0; mi < 4; mi++) {
        #pragma unroll
        for (int h = 0; h < 2; h++) {
            int o = o0 + wm * 64 + mi * 16 + g + h * 8;
            int head = o / 192, rem = o - head * 192;
            int part = rem >> 6, c = rem & 63;
            float bv = __ldg(bias + o);
            float* base = g_qkv + (size_t)((b * NH + head) * 3 + part) * HWn * DH;
            if (part < 2) {
                float* dst = base + c;
                #pragma unroll
                for (int ni = 0; ni < 4; ni++) {
                    int s = n0 + wn * 32 + ni * 8 + 2 * tig;
                    dst[(size_t)s * DH]       = acc[mi][ni][h * 2 + 0] + bv;
                    dst[(size_t)(s + 1) * DH] = acc[mi][ni][h * 2 + 1] + bv;
                }
            } else {                       // V: transposed [c][s], float2 stores
                float* dst = base + (size_t)c * HWn;
                #pragma unroll
                for (int ni = 0; ni < 4; ni++) {
                    int s = n0 + wn * 32 + ni * 8 + 2 * tig;
                    float2 ov;
                    ov.x = acc[mi][ni][h * 2 + 0] + bv;
                    ov.y = acc[mi][ni][h * 2 + 1] + bv;
                    *(float2*)&dst[s] = ov;
                }
            }
        }
    }
}

// ---------------------------------------------------------------------------
// Kernel 3: flash attention, tf32 HMMA, cp.async 2-stage K/V.
// Block = (bh, 64-query tile), 4 warps. Dyn smem 104448 B:
// Qs[64][68] @0, Ps[64][68] @4352, Ks[2][64][68] @8704, Vt[2][64][68] @17408.
// ---------------------------------------------------------------------------
__global__ __launch_bounds__(128) void attn_mma_kernel() {
    extern __shared__ uint32_t smn[];
    uint32_t sb = smem_u32(smn);
    const uint32_t* Qs = smn;
    uint32_t* Ps = smn + 4352;

    int bh = blockIdx.y;
    int q0 = blockIdx.x << 6;
    int tid = threadIdx.x;
    int w = tid >> 5, lane = tid & 31;
    int g = lane >> 2, tig = lane & 3;

    const float* qp = g_qkv + ((size_t)bh * 3 * HWn + q0) * DH;
    const float* kp = g_qkv + (size_t)(bh * 3 + 1) * HWn * DH;
    const float* vp = g_qkv + (size_t)(bh * 3 + 2) * HWn * DH;  // [dh][s]
    const float scale = 0.044194173824159216f;   // 512^-0.5

    // prologue: Q + tile-0 K/V, one commit group
    #pragma unroll
    for (int i = 0; i < 8; i++) {
        int id = tid + i * 128;
        int r = id >> 4, q = id & 15;
        CP16(sb + (uint32_t)(r * 68 + q * 4) * 4, qp + r * DH + q * 4);
        CP16(sb + (uint32_t)(8704 + r * 68 + q * 4) * 4, kp + r * DH + q * 4);
        CP16(sb + (uint32_t)(17408 + r * 68 + q * 4) * 4, vp + (size_t)r * HWn + q * 4);
    }
    CP_COMMIT();

    float oacc[8][4];
    #pragma unroll
    for (int nd = 0; nd < 8; nd++)
        #pragma unroll
        for (int c = 0; c < 4; c++) oacc[nd][c] = 0.f;
    float m0 = -1e30f, m1 = -1e30f, l0 = 0.f, l1 = 0.f;

    const int row = w * 16 + g;

    #pragma unroll 1
    for (int t = 0; t < 16; t++) {
        const int st = t & 1;
        if (t + 1 < 16) {
            const float* kpt = kp + (size_t)(t + 1) * 64 * DH;
            const float* vpt = vp + (t + 1) * 64;
            uint32_t ko = 8704 + (st ^ 1) * 4352;
            uint32_t vo = 17408 + (st ^ 1) * 4352;
            #pragma unroll
            for (int i = 0; i < 8; i++) {
                int id = tid + i * 128;
                int r = id >> 4, q = id & 15;
                CP16(sb + (ko + r * 68 + q * 4) * 4, kpt + r * DH + q * 4);
                CP16(sb + (vo + r * 68 + q * 4) * 4, vpt + (size_t)r * HWn + q * 4);
            }
            CP_COMMIT();
            CP_WAIT1();
        } else {
            CP_WAIT0();
        }
        __syncthreads();
        const uint32_t* Ks = smn + 8704 + st * 4352;
        const uint32_t* Vt = smn + 17408 + st * 4352;

        // ---- S = Q @ K^T ----
        float sacc[8][4];
        #pragma unroll
        for (int ni = 0; ni < 8; ni++)
            #pragma unroll
            for (int c = 0; c < 4; c++) sacc[ni][c] = 0.f;
        #pragma unroll
        for (int kk = 0; kk < 8; kk++) {
            uint32_t af[4];
            af[0] = Qs[row * 68 + kk * 8 + tig];
            af[1] = Qs[(row + 8) * 68 + kk * 8 + tig];
            af[2] = Qs[row * 68 + kk * 8 + tig + 4];
            af[3] = Qs[(row + 8) * 68 + kk * 8 + tig + 4];
            #pragma unroll
            for (int ni = 0; ni < 8; ni++) {
                uint32_t bf[2];
                bf[0] = Ks[(ni * 8 + g) * 68 + kk * 8 + tig];
                bf[1] = Ks[(ni * 8 + g) * 68 + kk * 8 + tig + 4];
                MMA_TF32(sacc[ni], af, bf);
            }
        }
        #pragma unroll
        for (int ni = 0; ni < 8; ni++)
            #pragma unroll
            for (int c = 0; c < 4; c++) sacc[ni][c] *= scale;

        // ---- online softmax (rows g, g+8) ----
        float mx0 = -1e30f, mx1 = -1e30f;
        #pragma unroll
        for (int ni = 0; ni < 8; ni++) {
            mx0 = fmaxf(mx0, fmaxf(sacc[ni][0], sacc[ni][1]));
            mx1 = fmaxf(mx1, fmaxf(sacc[ni][2], sacc[ni][3]));
        }
        mx0 = fmaxf(mx0, __shfl_xor_sync(0xffffffffu, mx0, 1));
        mx0 = fmaxf(mx0, __shfl_xor_sync(0xffffffffu, mx0, 2));
        mx1 = fmaxf(mx1, __shfl_xor_sync(0xffffffffu, mx1, 1));
        mx1 = fmaxf(mx1, __shfl_xor_sync(0xffffffffu, mx1, 2));
        float mn0 = fmaxf(m0, mx0), mn1 = fmaxf(m1, mx1);
        float al0 = __expf(m0 - mn0), al1 = __expf(m1 - mn1);
        float rs0 = 0.f, rs1 = 0.f;
        #pragma unroll
        for (int ni = 0; ni < 8; ni++) {
            sacc[ni][0] = __expf(sacc[ni][0] - mn0); rs0 += sacc[ni][0];
            sacc[ni][1] = __expf(sacc[ni][1] - mn0); rs0 += sacc[ni][1];
            sacc[ni][2] = __expf(sacc[ni][2] - mn1); rs1 += sacc[ni][2];
            sacc[ni][3] = __expf(sacc[ni][3] - mn1); rs1 += sacc[ni][3];
        }
        rs0 += __shfl_xor_sync(0xffffffffu, rs0, 1);
        rs0 += __shfl_xor_sync(0xffffffffu, rs0, 2);
        rs1 += __shfl_xor_sync(0xffffffffu, rs1, 1);
        rs1 += __shfl_xor_sync(0xffffffffu, rs1, 2);
        l0 = l0 * al0 + rs0; m0 = mn0;
        l1 = l1 * al1 + rs1; m1 = mn1;
        #pragma unroll
        for (int nd = 0; nd < 8; nd++) {
            oacc[nd][0] *= al0; oacc[nd][1] *= al0;
            oacc[nd][2] *= al1; oacc[nd][3] *= al1;
        }

        // ---- P -> smem (per-warp rows; raw f32) ----
        #pragma unroll
        for (int ni = 0; ni < 8; ni++) {
            Ps[row * 68 + ni * 8 + 2 * tig]           = __float_as_uint(sacc[ni][0]);
            Ps[row * 68 + ni * 8 + 2 * tig + 1]       = __float_as_uint(sacc[ni][1]);
            Ps[(row + 8) * 68 + ni * 8 + 2 * tig]     = __float_as_uint(sacc[ni][2]);
            Ps[(row + 8) * 68 + ni * 8 + 2 * tig + 1] = __float_as_uint(sacc[ni][3]);
        }
        __syncwarp();

        // ---- O += P @ V  (Vt is true V^T [dh][key], stride 68) ----
        #pragma unroll
        for (int kk = 0; kk < 8; kk++) {
            uint32_t af[4];
            af[0] = Ps[row * 68 + kk * 8 + tig];
            af[1] = Ps[(row + 8) * 68 + kk * 8 + tig];
            af[2] = Ps[row * 68 + kk * 8 + tig + 4];
            af[3] = Ps[(row + 8) * 68 + kk * 8 + tig + 4];
            #pragma unroll
            for (int nd = 0; nd < 8; nd++) {
                int dn = nd * 8 + g;
                uint32_t bf[2];
                bf[0] = Vt[dn * 68 + kk * 8 + tig];
                bf[1] = Vt[dn * 68 + kk * 8 + tig + 4];
                MMA_TF32(oacc[nd], af, bf);
            }
        }
        __syncthreads();   // protect stage st from t+1's cp.async overwrite
    }

    // ---- epilogue: /l, head-major scramble, float2 stores ----
    float il0 = 1.f / l0, il1 = 1.f / l1;
    int bp  = bh & 15;
    int ch0 = (bh >> 4) << 6;
    int s0 = q0 + row;
    #pragma unroll
    for (int nd = 0; nd < 8; nd++) {
        int c = ch0 + nd * 8 + 2 * tig;
        float2 v0, v1;
        v0.x = oacc[nd][0] * il0; v0.y = oacc[nd][1] * il0;
        v1.x = oacc[nd][2] * il1; v1.y = oacc[nd][3] * il1;
        *(float2*)(g_attn + ((size_t)(bp * HWn + s0)) * Cc + c)     = v0;
        *(float2*)(g_attn + ((size_t)(bp * HWn + s0 + 8)) * Cc + c) = v1;
    }
}

// ---------------------------------------------------------------------------
// Kernel 4: out = W_proj @ attn + bias + x.
// ---------------------------------------------------------------------------
__global__ __launch_bounds__(256) void proj_mma_kernel(const float* __restrict__ W,
                                                       const float* __restrict__ bias,
                                                       const float* __restrict__ x,
                                                       float* __restrict__ out) {
    int b = blockIdx.z, o0 = blockIdx.x * 128, n0 = blockIdx.y * 128;
    const float* Arow = W + (size_t)o0 * Cc;
    const float* Brow = g_attn + ((size_t)b * HWn + n0) * Cc;
    float acc[4][4][4];
    gemm_mainloop(Arow, Brow, acc);

    const int warp = threadIdx.x >> 5, lane = threadIdx.x & 31;
    const int wm = warp & 1, wn = warp >> 1;
    const int g = lane >> 2, tig = lane & 3;
    #pragma unroll
    for (int mi = 0; mi < 4; mi++) {
        #pragma unroll
        for (int h = 0; h < 2; h++) {
            int o = o0 + wm * 64 + mi * 16 + g + h * 8;
            float bv = __ldg(bias + o);
            size_t rowoff = (size_t)(b * Cc + o) * HWn;
            #pragma unroll
            for (int ni = 0; ni < 4; ni++) {
                int s = n0 + wn * 32 + ni * 8 + 2 * tig;
                float2 xv = *(const float2*)&x[rowoff + s];
                float2 ov;
                ov.x = acc[mi][ni][h * 2 + 0] + bv + xv.x;
                ov.y = acc[mi][ni][h * 2 + 1] + bv + xv.y;
                *(float2*)&out[rowoff + s] = ov;
            }
        }
    }
}

// ---------------------------------------------------------------------------
extern "C" void kernel_launch(void* const* d_in, const int* in_sizes, int n_in,
                              void* d_out, int out_size) {
    const float* x      = (const float*)d_in[0];
    const float* gamma  = (const float*)d_in[1];
    const float* beta   = (const float*)d_in[2];
    const float* w_qkv  = (const float*)d_in[3];
    const float* b_qkv  = (const float*)d_in[4];
    const float* w_proj = (const float*)d_in[5];
    const float* b_proj = (const float*)d_in[6];
    float* out = (float*)d_out;

    const int GEMM_SMEM = 73728;     // 2 stages x (A+B) x 128x36 floats
    const int ATTN_SMEM = 104448;    // Qs + Ps + 2x(Ks+Vt), stride 68
    cudaFuncSetAttribute(qkv_mma_kernel,
                         cudaFuncAttributeMaxDynamicSharedMemorySize, GEMM_SMEM);
    cudaFuncSetAttribute(proj_mma_kernel,
                         cudaFuncAttributeMaxDynamicSharedMemorySize, GEMM_SMEM);
    cudaFuncSetAttribute(attn_mma_kernel,
                         cudaFuncAttributeMaxDynamicSharedMemorySize, ATTN_SMEM);

    gn_kernel<<<Bn * 32, 256>>>(x, gamma, beta);
    qkv_mma_kernel<<<dim3(12, 8, Bn), 256, GEMM_SMEM>>>(w_qkv, b_qkv);
    attn_mma_kernel<<<dim3(HWn / 64, Bn * NH), 128, ATTN_SMEM>>>();
    proj_mma_kernel<<<dim3(4, 8, Bn), 256, GEMM_SMEM>>>(w_proj, b_proj, x, out);
}

// round 6
// speedup vs baseline: 3.6164x; 1.1249x over previous
#include <cuda_runtime.h>
#include <cstdint>

#define Bn   16
#define Cc   512
#define HWn  1024
#define NH   8
#define DH   64

// Scratch (static device arrays — no cudaMalloc)
__device__ float g_ht[Bn * HWn * Cc];                // h^T  [b][hw][c]
__device__ float g_qkv[Bn * NH * 3 * HWn * DH];      // q,k: [bh][p][s][c]; v: [bh][2][c][s]
__device__ float g_attn[Bn * HWn * Cc];              // attn out [b][s][c]

// ---------------------------------------------------------------------------
// PTX helpers (sm_80-era — compiles for plain sm_103 target)
// ---------------------------------------------------------------------------
__device__ __forceinline__ uint32_t smem_u32(const void* p) {
    uint32_t a;
    asm("{ .reg .u64 t; cvta.to.shared.u64 t, %1; cvt.u32.u64 %0, t; }" : "=r"(a) : "l"(p));
    return a;
}
#define CP16(dst, src)                                                        \
    asm volatile("cp.async.cg.shared.global [%0], [%1], 16;"                  \
                 :: "r"(dst), "l"(src))
#define CP_COMMIT() asm volatile("cp.async.commit_group;" ::: "memory")
#define CP_WAIT1()  asm volatile("cp.async.wait_group 1;" ::: "memory")
#define CP_WAIT0()  asm volatile("cp.async.wait_group 0;" ::: "memory")

// raw-f32 operands: tf32 HMMA truncates low mantissa bits in hardware
#define MMA_TF32(c, a, bfr)                                                   \
    asm volatile(                                                             \
        "mma.sync.aligned.m16n8k8.row.col.f32.tf32.tf32.f32 "                 \
        "{%0,%1,%2,%3}, {%4,%5,%6,%7}, {%8,%9}, {%0,%1,%2,%3};"               \
        : "+f"((c)[0]), "+f"((c)[1]), "+f"((c)[2]), "+f"((c)[3])              \
        : "r"((a)[0]), "r"((a)[1]), "r"((a)[2]), "r"((a)[3]),                 \
          "r"((bfr)[0]), "r"((bfr)[1]))

// ---------------------------------------------------------------------------
// Warp-MMA GEMM mainloop, cp.async 3-stage: D[128x128] = A[128x512]*B[128x512]^T
// 8 warps (2m x 4n), warp tile 64x32, k-tile 32. Dyn smem: 3 stages A+B,
// stride 36 (fragment banks 4g+tig conflict-free). ONE barrier per k-tile.
// Smem words: A st*4608, B 13824 + st*4608. Total 27648 w = 110592 B.
// ---------------------------------------------------------------------------
__device__ __forceinline__ void gemm_fill(uint32_t sb, int st,
                                          const float* __restrict__ Arow,
                                          const float* __restrict__ Brow,
                                          int k0, int tid) {
    #pragma unroll
    for (int i = 0; i < 4; i++) {
        int id = tid + i * 256;
        int r = id >> 3, q = id & 7;
        CP16(sb + (uint32_t)(st * 4608 + r * 36 + q * 4) * 4,
             Arow + (size_t)r * Cc + k0 + q * 4);
        CP16(sb + (uint32_t)(13824 + st * 4608 + r * 36 + q * 4) * 4,
             Brow + (size_t)r * Cc + k0 + q * 4);
    }
}

__device__ __forceinline__ void gemm_mainloop(const float* __restrict__ Arow,
                                              const float* __restrict__ Brow,
                                              float acc[4][4][4]) {
    extern __shared__ uint32_t gsm[];
    uint32_t sb = smem_u32(gsm);
    const int tid = threadIdx.x;
    const int warp = tid >> 5, lane = tid & 31;
    const int wm = warp & 1, wn = warp >> 1;
    const int g = lane >> 2, tig = lane & 3;

    #pragma unroll
    for (int mi = 0; mi < 4; mi++)
        #pragma unroll
        for (int ni = 0; ni < 4; ni++)
            #pragma unroll
            for (int c = 0; c < 4; c++) acc[mi][ni][c] = 0.f;

    gemm_fill(sb, 0, Arow, Brow, 0, tid);
    CP_COMMIT();
    gemm_fill(sb, 1, Arow, Brow, 32, tid);
    CP_COMMIT();

    #pragma unroll 1
    for (int it = 0; it < 16; it++) {
        if (it < 15) { CP_WAIT1(); } else { CP_WAIT0(); }
        __syncthreads();
        if (it + 2 < 16) {
            gemm_fill(sb, (it + 2) % 3, Arow, Brow, (it + 2) * 32, tid);
            CP_COMMIT();
        }
        const int st = it % 3;
        const uint32_t* As = gsm + st * 4608;
        const uint32_t* Bs = gsm + 13824 + st * 4608;
        #pragma unroll
        for (int kk = 0; kk < 32; kk += 8) {
            uint32_t af[4][4], bf[4][2];
            #pragma unroll
            for (int mi = 0; mi < 4; mi++) {
                int r = wm * 64 + mi * 16 + g;
                af[mi][0] = As[r * 36 + kk + tig];
                af[mi][1] = As[(r + 8) * 36 + kk + tig];
                af[mi][2] = As[r * 36 + kk + tig + 4];
                af[mi][3] = As[(r + 8) * 36 + kk + tig + 4];
            }
            #pragma unroll
            for (int ni = 0; ni < 4; ni++) {
                int r = wn * 32 + ni * 8 + g;
                bf[ni][0] = Bs[r * 36 + kk + tig];
                bf[ni][1] = Bs[r * 36 + kk + tig + 4];
            }
            #pragma unroll
            for (int mi = 0; mi < 4; mi++)
                #pragma unroll
                for (int ni = 0; ni < 4; ni++)
                    MMA_TF32(acc[mi][ni], af[mi], bf[ni]);
        }
    }
}

// ---------------------------------------------------------------------------
// Kernel 1: GroupNorm -> g_ht[b][hw][c].
// ---------------------------------------------------------------------------
__global__ __launch_bounds__(256) void gn_kernel(const float* __restrict__ x,
                                                 const float* __restrict__ gamma,
                                                 const float* __restrict__ beta) {
    int b = blockIdx.x >> 5;
    int g = blockIdx.x & 31;
    int tid = threadIdx.x;
    size_t base = (size_t)(b * Cc + g * 16) * HWn;
    const float4* xp = (const float4*)(x + base);
    const int N4 = 16 * HWn / 4;

    float s = 0.f, ss = 0.f;
    for (int i = tid; i < N4; i += 256) {
        float4 v = xp[i];
        s  += v.x + v.y + v.z + v.w;
        ss += v.x * v.x + v.y * v.y + v.z * v.z + v.w * v.w;
    }
    __shared__ float rs_[8], rss_[8];
    __shared__ float ga_s[16], be_s[16];
    __shared__ float tile[16][68];
    #pragma unroll
    for (int o = 16; o; o >>= 1) {
        s  += __shfl_xor_sync(0xffffffffu, s, o);
        ss += __shfl_xor_sync(0xffffffffu, ss, o);
    }
    int wid = tid >> 5, lid = tid & 31;
    if (lid == 0) { rs_[wid] = s; rss_[wid] = ss; }
    __syncthreads();
    if (tid < 32) {
        s = rs_[lid & 7]; ss = rss_[lid & 7];
        #pragma unroll
        for (int o = 4; o; o >>= 1) {
            s  += __shfl_xor_sync(0xffffffffu, s, o);
            ss += __shfl_xor_sync(0xffffffffu, ss, o);
        }
        if (lid == 0) { rs_[0] = s; rss_[0] = ss; }
    }
    __syncthreads();
    float mean = rs_[0] * (1.f / 16384.f);
    float var  = rss_[0] * (1.f / 16384.f) - mean * mean;
    float inv  = rsqrtf(var + 1e-5f);
    if (tid < 16) {
        float ga = gamma[g * 16 + tid] * inv;
        ga_s[tid] = ga;
        be_s[tid] = beta[g * 16 + tid] - mean * ga;
    }
    __syncthreads();

    float* outb = g_ht + (size_t)b * HWn * Cc + g * 16;
    int c = tid >> 4, q = tid & 15;
    int hw = tid >> 2, cq = tid & 3;
    for (int hw0 = 0; hw0 < HWn; hw0 += 64) {
        float4 v = xp[c * 256 + (hw0 >> 2) + q];
        float ga = ga_s[c], be = be_s[c];
        float4 o4;
        o4.x = v.x * ga + be; o4.y = v.y * ga + be;
        o4.z = v.z * ga + be; o4.w = v.w * ga + be;
        *(float4*)&tile[c][q << 2] = o4;
        __syncthreads();
        float4 w4;
        w4.x = tile[4 * cq + 0][hw];
        w4.y = tile[4 * cq + 1][hw];
        w4.z = tile[4 * cq + 2][hw];
        w4.w = tile[4 * cq + 3][hw];
        *(float4*)(outb + (size_t)(hw0 + hw) * Cc + 4 * cq) = w4;
        __syncthreads();
    }
}

// ---------------------------------------------------------------------------
// Kernel 2: qkv GEMM. q,k parts -> [s][c]; v part -> TRANSPOSED [c][s].
// ---------------------------------------------------------------------------
__global__ __launch_bounds__(256) void qkv_mma_kernel(const float* __restrict__ W,
                                                      const float* __restrict__ bias) {
    int b = blockIdx.z, o0 = blockIdx.x * 128, n0 = blockIdx.y * 128;
    const float* Arow = W + (size_t)o0 * Cc;
    const float* Brow = g_ht + ((size_t)b * HWn + n0) * Cc;
    float acc[4][4][4];
    gemm_mainloop(Arow, Brow, acc);

    const int warp = threadIdx.x >> 5, lane = threadIdx.x & 31;
    const int wm = warp & 1, wn = warp >> 1;
    const int g = lane >> 2, tig = lane & 3;
    #pragma unroll
    for (int mi = 0; mi < 4; mi++) {
        #pragma unroll
        for (int h = 0; h < 2; h++) {
            int o = o0 + wm * 64 + mi * 16 + g + h * 8;
            int head = o / 192, rem = o - head * 192;
            int part = rem >> 6, c = rem & 63;
            float bv = __ldg(bias + o);
            float* base = g_qkv + (size_t)((b * NH + head) * 3 + part) * HWn * DH;
            if (part < 2) {
                float* dst = base + c;
                #pragma unroll
                for (int ni = 0; ni < 4; ni++) {
                    int s = n0 + wn * 32 + ni * 8 + 2 * tig;
                    dst[(size_t)s * DH]       = acc[mi][ni][h * 2 + 0] + bv;
                    dst[(size_t)(s + 1) * DH] = acc[mi][ni][h * 2 + 1] + bv;
                }
            } else {                       // V: transposed [c][s], float2 stores
                float* dst = base + (size_t)c * HWn;
                #pragma unroll
                for (int ni = 0; ni < 4; ni++) {
                    int s = n0 + wn * 32 + ni * 8 + 2 * tig;
                    float2 ov;
                    ov.x = acc[mi][ni][h * 2 + 0] + bv;
                    ov.y = acc[mi][ni][h * 2 + 1] + bv;
                    *(float2*)&dst[s] = ov;
                }
            }
        }
    }
}

// ---------------------------------------------------------------------------
// Kernel 3: flash attention, tf32 HMMA, 128-query blocks, 8 warps,
// cp.async 3-stage K/V (ONE barrier per key-tile).
// Dyn smem words: Qs[128][68] @0, Ps[128][68] @8704,
//                 Ks[3][64][68] @17408, Vt[3][64][68] @30464. 174080 B.
// ---------------------------------------------------------------------------
__global__ __launch_bounds__(256) void attn_mma_kernel() {
    extern __shared__ uint32_t smn[];
    uint32_t sb = smem_u32(smn);
    const uint32_t* Qs = smn;
    uint32_t* Ps = smn + 8704;

    int bh = blockIdx.y;
    int q0 = blockIdx.x << 7;
    int tid = threadIdx.x;
    int w = tid >> 5, lane = tid & 31;
    int g = lane >> 2, tig = lane & 3;

    const float* qp = g_qkv + ((size_t)bh * 3 * HWn + q0) * DH;
    const float* kp = g_qkv + (size_t)(bh * 3 + 1) * HWn * DH;
    const float* vp = g_qkv + (size_t)(bh * 3 + 2) * HWn * DH;  // [dh][s]
    const float scale = 0.044194173824159216f;   // 512^-0.5

    // prologue: Q (128 rows) + tile0 K/V in group 0; tile1 K/V in group 1
    #pragma unroll
    for (int i = 0; i < 8; i++) {
        int id = tid + i * 256;
        int r = id >> 4, q = id & 15;
        CP16(sb + (uint32_t)(r * 68 + q * 4) * 4, qp + r * DH + q * 4);
    }
    #pragma unroll
    for (int i = 0; i < 4; i++) {
        int id = tid + i * 256;
        int r = id >> 4, q = id & 15;
        CP16(sb + (uint32_t)(17408 + r * 68 + q * 4) * 4, kp + r * DH + q * 4);
        CP16(sb + (uint32_t)(30464 + r * 68 + q * 4) * 4, vp + (size_t)r * HWn + q * 4);
    }
    CP_COMMIT();
    #pragma unroll
    for (int i = 0; i < 4; i++) {
        int id = tid + i * 256;
        int r = id >> 4, q = id & 15;
        CP16(sb + (uint32_t)(17408 + 4352 + r * 68 + q * 4) * 4,
             kp + (size_t)(64 + r) * DH + q * 4);
        CP16(sb + (uint32_t)(30464 + 4352 + r * 68 + q * 4) * 4,
             vp + (size_t)r * HWn + 64 + q * 4);
    }
    CP_COMMIT();

    float oacc[8][4];
    #pragma unroll
    for (int nd = 0; nd < 8; nd++)
        #pragma unroll
        for (int c = 0; c < 4; c++) oacc[nd][c] = 0.f;
    float m0 = -1e30f, m1 = -1e30f, l0 = 0.f, l1 = 0.f;

    const int row = w * 16 + g;

    #pragma unroll 1
    for (int t = 0; t < 16; t++) {
        if (t < 15) { CP_WAIT1(); } else { CP_WAIT0(); }
        __syncthreads();
        if (t + 2 < 16) {
            int st2 = (t + 2) % 3;
            const float* kpt = kp + (size_t)(t + 2) * 64 * DH;
            const float* vpt = vp + (t + 2) * 64;
            uint32_t ko = 17408 + st2 * 4352;
            uint32_t vo = 30464 + st2 * 4352;
            #pragma unroll
            for (int i = 0; i < 4; i++) {
                int id = tid + i * 256;
                int r = id >> 4, q = id & 15;
                CP16(sb + (ko + r * 68 + q * 4) * 4, kpt + r * DH + q * 4);
                CP16(sb + (vo + r * 68 + q * 4) * 4, vpt + (size_t)r * HWn + q * 4);
            }
            CP_COMMIT();
        }
        const int st = t % 3;
        const uint32_t* Ks = smn + 17408 + st * 4352;
        const uint32_t* Vt = smn + 30464 + st * 4352;

        // ---- S = Q @ K^T (16 q-rows x 64 keys per warp) ----
        float sacc[8][4];
        #pragma unroll
        for (int ni = 0; ni < 8; ni++)
            #pragma unroll
            for (int c = 0; c < 4; c++) sacc[ni][c] = 0.f;
        #pragma unroll
        for (int kk = 0; kk < 8; kk++) {
            uint32_t af[4];
            af[0] = Qs[row * 68 + kk * 8 + tig];
            af[1] = Qs[(row + 8) * 68 + kk * 8 + tig];
            af[2] = Qs[row * 68 + kk * 8 + tig + 4];
            af[3] = Qs[(row + 8) * 68 + kk * 8 + tig + 4];
            #pragma unroll
            for (int ni = 0; ni < 8; ni++) {
                uint32_t bf[2];
                bf[0] = Ks[(ni * 8 + g) * 68 + kk * 8 + tig];
                bf[1] = Ks[(ni * 8 + g) * 68 + kk * 8 + tig + 4];
                MMA_TF32(sacc[ni], af, bf);
            }
        }
        #pragma unroll
        for (int ni = 0; ni < 8; ni++)
            #pragma unroll
            for (int c = 0; c < 4; c++) sacc[ni][c] *= scale;

        // ---- online softmax (rows g, g+8) ----
        float mx0 = -1e30f, mx1 = -1e30f;
        #pragma unroll
        for (int ni = 0; ni < 8; ni++) {
            mx0 = fmaxf(mx0, fmaxf(sacc[ni][0], sacc[ni][1]));
            mx1 = fmaxf(mx1, fmaxf(sacc[ni][2], sacc[ni][3]));
        }
        mx0 = fmaxf(mx0, __shfl_xor_sync(0xffffffffu, mx0, 1));
        mx0 = fmaxf(mx0, __shfl_xor_sync(0xffffffffu, mx0, 2));
        mx1 = fmaxf(mx1, __shfl_xor_sync(0xffffffffu, mx1, 1));
        mx1 = fmaxf(mx1, __shfl_xor_sync(0xffffffffu, mx1, 2));
        float mn0 = fmaxf(m0, mx0), mn1 = fmaxf(m1, mx1);
        float al0 = __expf(m0 - mn0), al1 = __expf(m1 - mn1);
        float rs0 = 0.f, rs1 = 0.f;
        #pragma unroll
        for (int ni = 0; ni < 8; ni++) {
            sacc[ni][0] = __expf(sacc[ni][0] - mn0); rs0 += sacc[ni][0];
            sacc[ni][1] = __expf(sacc[ni][1] - mn0); rs0 += sacc[ni][1];
            sacc[ni][2] = __expf(sacc[ni][2] - mn1); rs1 += sacc[ni][2];
            sacc[ni][3] = __expf(sacc[ni][3] - mn1); rs1 += sacc[ni][3];
        }
        rs0 += __shfl_xor_sync(0xffffffffu, rs0, 1);
        rs0 += __shfl_xor_sync(0xffffffffu, rs0, 2);
        rs1 += __shfl_xor_sync(0xffffffffu, rs1, 1);
        rs1 += __shfl_xor_sync(0xffffffffu, rs1, 2);
        l0 = l0 * al0 + rs0; m0 = mn0;
        l1 = l1 * al1 + rs1; m1 = mn1;
        #pragma unroll
        for (int nd = 0; nd < 8; nd++) {
            oacc[nd][0] *= al0; oacc[nd][1] *= al0;
            oacc[nd][2] *= al1; oacc[nd][3] *= al1;
        }

        // ---- P -> smem (per-warp rows; raw f32) ----
        #pragma unroll
        for (int ni = 0; ni < 8; ni++) {
            Ps[row * 68 + ni * 8 + 2 * tig]           = __float_as_uint(sacc[ni][0]);
            Ps[row * 68 + ni * 8 + 2 * tig + 1]       = __float_as_uint(sacc[ni][1]);
            Ps[(row + 8) * 68 + ni * 8 + 2 * tig]     = __float_as_uint(sacc[ni][2]);
            Ps[(row + 8) * 68 + ni * 8 + 2 * tig + 1] = __float_as_uint(sacc[ni][3]);
        }
        __syncwarp();

        // ---- O += P @ V  (Vt = V^T [dh][key], stride 68) ----
        #pragma unroll
        for (int kk = 0; kk < 8; kk++) {
            uint32_t af[4];
            af[0] = Ps[row * 68 + kk * 8 + tig];
            af[1] = Ps[(row + 8) * 68 + kk * 8 + tig];
            af[2] = Ps[row * 68 + kk * 8 + tig + 4];
            af[3] = Ps[(row + 8) * 68 + kk * 8 + tig + 4];
            #pragma unroll
            for (int nd = 0; nd < 8; nd++) {
                int dn = nd * 8 + g;
                uint32_t bf[2];
                bf[0] = Vt[dn * 68 + kk * 8 + tig];
                bf[1] = Vt[dn * 68 + kk * 8 + tig + 4];
                MMA_TF32(oacc[nd], af, bf);
            }
        }
    }

    // ---- epilogue: /l, head-major scramble, float2 stores ----
    float il0 = 1.f / l0, il1 = 1.f / l1;
    int bp  = bh & 15;
    int ch0 = (bh >> 4) << 6;
    int s0 = q0 + row;
    #pragma unroll
    for (int nd = 0; nd < 8; nd++) {
        int c = ch0 + nd * 8 + 2 * tig;
        float2 v0, v1;
        v0.x = oacc[nd][0] * il0; v0.y = oacc[nd][1] * il0;
        v1.x = oacc[nd][2] * il1; v1.y = oacc[nd][3] * il1;
        *(float2*)(g_attn + ((size_t)(bp * HWn + s0)) * Cc + c)     = v0;
        *(float2*)(g_attn + ((size_t)(bp * HWn + s0 + 8)) * Cc + c) = v1;
    }
}

// ---------------------------------------------------------------------------
// Kernel 4: out = W_proj @ attn + bias + x.
// ---------------------------------------------------------------------------
__global__ __launch_bounds__(256) void proj_mma_kernel(const float* __restrict__ W,
                                                       const float* __restrict__ bias,
                                                       const float* __restrict__ x,
                                                       float* __restrict__ out) {
    int b = blockIdx.z, o0 = blockIdx.x * 128, n0 = blockIdx.y * 128;
    const float* Arow = W + (size_t)o0 * Cc;
    const float* Brow = g_attn + ((size_t)b * HWn + n0) * Cc;
    float acc[4][4][4];
    gemm_mainloop(Arow, Brow, acc);

    const int warp = threadIdx.x >> 5, lane = threadIdx.x & 31;
    const int wm = warp & 1, wn = warp >> 1;
    const int g = lane >> 2, tig = lane & 3;
    #pragma unroll
    for (int mi = 0; mi < 4; mi++) {
        #pragma unroll
        for (int h = 0; h < 2; h++) {
            int o = o0 + wm * 64 + mi * 16 + g + h * 8;
            float bv = __ldg(bias + o);
            size_t rowoff = (size_t)(b * Cc + o) * HWn;
            #pragma unroll
            for (int ni = 0; ni < 4; ni++) {
                int s = n0 + wn * 32 + ni * 8 + 2 * tig;
                float2 xv = *(const float2*)&x[rowoff + s];
                float2 ov;
                ov.x = acc[mi][ni][h * 2 + 0] + bv + xv.x;
                ov.y = acc[mi][ni][h * 2 + 1] + bv + xv.y;
                *(float2*)&out[rowoff + s] = ov;
            }
        }
    }
}

// ---------------------------------------------------------------------------
extern "C" void kernel_launch(void* const* d_in, const int* in_sizes, int n_in,
                              void* d_out, int out_size) {
    const float* x      = (const float*)d_in[0];
    const float* gamma  = (const float*)d_in[1];
    const float* beta   = (const float*)d_in[2];
    const float* w_qkv  = (const float*)d_in[3];
    const float* b_qkv  = (const float*)d_in[4];
    const float* w_proj = (const float*)d_in[5];
    const float* b_proj = (const float*)d_in[6];
    float* out = (float*)d_out;

    const int GEMM_SMEM = 110592;    // 3 stages x (A+B) x 128x36 floats
    const int ATTN_SMEM = 174080;    // Qs + Ps (128q) + 3x(Ks+Vt)
    cudaFuncSetAttribute(qkv_mma_kernel,
                         cudaFuncAttributeMaxDynamicSharedMemorySize, GEMM_SMEM);
    cudaFuncSetAttribute(proj_mma_kernel,
                         cudaFuncAttributeMaxDynamicSharedMemorySize, GEMM_SMEM);
    cudaFuncSetAttribute(attn_mma_kernel,
                         cudaFuncAttributeMaxDynamicSharedMemorySize, ATTN_SMEM);

    gn_kernel<<<Bn * 32, 256>>>(x, gamma, beta);
    qkv_mma_kernel<<<dim3(12, 8, Bn), 256, GEMM_SMEM>>>(w_qkv, b_qkv);
    attn_mma_kernel<<<dim3(HWn / 128, Bn * NH), 256, ATTN_SMEM>>>();
    proj_mma_kernel<<<dim3(4, 8, Bn), 256, GEMM_SMEM>>>(w_proj, b_proj, x, out);
}

// round 7
// speedup vs baseline: 6.9662x; 1.9263x over previous
#include <cuda_runtime.h>
#include <cuda_fp16.h>
#include <cstdint>

#define Bn   16
#define Cc   512
#define HWn  1024
#define NH   8
#define DH   64

// Scratch (static device arrays — no cudaMalloc). All fp16.
__device__ __half g_ht[Bn * HWn * Cc];               // h^T  [b][hw][c]
__device__ __half g_qkv[Bn * NH * 3 * HWn * DH];     // q,k: [bh][p][s][c]; v: [bh][2][c][s]
__device__ __half g_attn[Bn * HWn * Cc];             // attn out [b][s][c]
__device__ __half g_wqkv[3 * Cc * Cc];               // fp16 copy of w_qkv
__device__ __half g_wproj[Cc * Cc];                  // fp16 copy of w_proj

// ---------------------------------------------------------------------------
// PTX helpers (sm_75/80-era — compile for plain sm_103 target)
// ---------------------------------------------------------------------------
__device__ __forceinline__ uint32_t smem_u32(const void* p) {
    uint32_t a;
    asm("{ .reg .u64 t; cvta.to.shared.u64 t, %1; cvt.u32.u64 %0, t; }" : "=r"(a) : "l"(p));
    return a;
}
#define CP16(dst, src)                                                        \
    asm volatile("cp.async.cg.shared.global [%0], [%1], 16;"                  \
                 :: "r"(dst), "l"(src))
#define CP_COMMIT() asm volatile("cp.async.commit_group;" ::: "memory")
#define CP_WAIT1()  asm volatile("cp.async.wait_group 1;" ::: "memory")
#define CP_WAIT0()  asm volatile("cp.async.wait_group 0;" ::: "memory")

#define LDSM_X4(r0, r1, r2, r3, a)                                            \
    asm volatile("ldmatrix.sync.aligned.m8n8.x4.shared.b16 {%0,%1,%2,%3}, [%4];" \
        : "=r"(r0), "=r"(r1), "=r"(r2), "=r"(r3) : "r"(a))

#define MMA_F16(c, a, bfr)                                                    \
    asm volatile(                                                             \
        "mma.sync.aligned.m16n8k16.row.col.f32.f16.f16.f32 "                  \
        "{%0,%1,%2,%3}, {%4,%5,%6,%7}, {%8,%9}, {%0,%1,%2,%3};"               \
        : "+f"((c)[0]), "+f"((c)[1]), "+f"((c)[2]), "+f"((c)[3])              \
        : "r"((a)[0]), "r"((a)[1]), "r"((a)[2]), "r"((a)[3]),                 \
          "r"((bfr)[0]), "r"((bfr)[1]))

__device__ __forceinline__ uint32_t pack_h2(float lo, float hi) {
    __half2 h = __floats2half2_rn(lo, hi);
    uint32_t u;
    memcpy(&u, &h, 4);
    return u;
}

// ---------------------------------------------------------------------------
// Weight fp32 -> fp16 converters (run every call; deterministic, ~5us)
// ---------------------------------------------------------------------------
__global__ __launch_bounds__(256) void cvt_wqkv_kernel(const float* __restrict__ w) {
    int i = (blockIdx.x * 256 + threadIdx.x) * 4;
    float4 v = *(const float4*)(w + i);
    *(__half2*)(g_wqkv + i)     = __floats2half2_rn(v.x, v.y);
    *(__half2*)(g_wqkv + i + 2) = __floats2half2_rn(v.z, v.w);
}
__global__ __launch_bounds__(256) void cvt_wproj_kernel(const float* __restrict__ w) {
    int i = (blockIdx.x * 256 + threadIdx.x) * 4;
    float4 v = *(const float4*)(w + i);
    *(__half2*)(g_wproj + i)     = __floats2half2_rn(v.x, v.y);
    *(__half2*)(g_wproj + i + 2) = __floats2half2_rn(v.z, v.w);
}

// ---------------------------------------------------------------------------
// fp16 warp-MMA GEMM mainloop, cp.async 3-stage, ldmatrix fragments.
// D[128x128] = A[128x512] * B[128x512]^T, both K-major fp16.
// 8 warps (2m x 4n), warp tile 64x32, k-tile 32 halves.
// Smem per stage: A 128 rows x 80B (64B data + 16 pad), B same.
// A st*10240, B 30720 + st*10240; total 61440 B.
// ldmatrix conflict-free: row stride 20 words -> 20r mod 32 partitions banks.
// ---------------------------------------------------------------------------
__device__ __forceinline__ void gemm_fill(uint32_t sb, int st,
                                          const __half* __restrict__ Arow,
                                          const __half* __restrict__ Brow,
                                          int k0, int tid) {
    #pragma unroll
    for (int i = 0; i < 2; i++) {
        int id = tid + i * 256;           // 0..511
        int r = id >> 2, q = id & 3;      // 128 rows x 4x16B
        CP16(sb + (uint32_t)(st * 10240 + r * 80 + q * 16),
             Arow + (size_t)r * Cc + k0 + q * 8);
        CP16(sb + (uint32_t)(30720 + st * 10240 + r * 80 + q * 16),
             Brow + (size_t)r * Cc + k0 + q * 8);
    }
}

__device__ __forceinline__ void gemm_mainloop(const __half* __restrict__ Arow,
                                              const __half* __restrict__ Brow,
                                              float acc[4][4][4]) {
    extern __shared__ char gsm[];
    uint32_t sb = smem_u32(gsm);
    const int tid = threadIdx.x;
    const int warp = tid >> 5, lane = tid & 31;
    const int wm = warp & 1, wn = warp >> 1;
    // ldmatrix per-lane addressing
    const int lrow = (lane & 7) + ((lane >> 3) & 1) * 8;   // A: m within 16
    const int lka  = ((lane >> 4) & 1) * 8;                // A: k halves
    const int brow = (lane & 7) + ((lane >> 4) & 1) * 8;   // B: n within 16
    const int lkb  = ((lane >> 3) & 1) * 8;                // B: k halves
    const uint32_t aBase = sb + (uint32_t)((wm * 64 + lrow) * 80 + lka * 2);
    const uint32_t bBase = sb + (uint32_t)(30720 + (wn * 32 + brow) * 80 + lkb * 2);

    #pragma unroll
    for (int mi = 0; mi < 4; mi++)
        #pragma unroll
        for (int ni = 0; ni < 4; ni++)
            #pragma unroll
            for (int c = 0; c < 4; c++) acc[mi][ni][c] = 0.f;

    gemm_fill(sb, 0, Arow, Brow, 0, tid);
    CP_COMMIT();
    gemm_fill(sb, 1, Arow, Brow, 32, tid);
    CP_COMMIT();

    #pragma unroll 1
    for (int it = 0; it < 16; it++) {
        if (it < 15) { CP_WAIT1(); } else { CP_WAIT0(); }
        __syncthreads();
        if (it + 2 < 16) {
            gemm_fill(sb, (it + 2) % 3, Arow, Brow, (it + 2) * 32, tid);
            CP_COMMIT();
        }
        const uint32_t so = (uint32_t)((it % 3) * 10240);
        #pragma unroll
        for (int kk = 0; kk < 2; kk++) {
            uint32_t af[4][4], bf[4][2];
            #pragma unroll
            for (int mi = 0; mi < 4; mi++)
                LDSM_X4(af[mi][0], af[mi][1], af[mi][2], af[mi][3],
                        aBase + so + mi * 1280 + kk * 32);
            #pragma unroll
            for (int p = 0; p < 2; p++) {
                uint32_t r0, r1, r2, r3;
                LDSM_X4(r0, r1, r2, r3, bBase + so + p * 1280 + kk * 32);
                bf[2 * p][0] = r0; bf[2 * p][1] = r1;
                bf[2 * p + 1][0] = r2; bf[2 * p + 1][1] = r3;
            }
            #pragma unroll
            for (int mi = 0; mi < 4; mi++)
                #pragma unroll
                for (int ni = 0; ni < 4; ni++)
                    MMA_F16(acc[mi][ni], af[mi], bf[ni]);
        }
    }
}

// ---------------------------------------------------------------------------
// Kernel 1: GroupNorm -> g_ht[b][hw][c] (fp16 out).
// ---------------------------------------------------------------------------
__global__ __launch_bounds__(256) void gn_kernel(const float* __restrict__ x,
                                                 const float* __restrict__ gamma,
                                                 const float* __restrict__ beta) {
    int b = blockIdx.x >> 5;
    int g = blockIdx.x & 31;
    int tid = threadIdx.x;
    size_t base = (size_t)(b * Cc + g * 16) * HWn;
    const float4* xp = (const float4*)(x + base);
    const int N4 = 16 * HWn / 4;

    float s = 0.f, ss = 0.f;
    for (int i = tid; i < N4; i += 256) {
        float4 v = xp[i];
        s  += v.x + v.y + v.z + v.w;
        ss += v.x * v.x + v.y * v.y + v.z * v.z + v.w * v.w;
    }
    __shared__ float rs_[8], rss_[8];
    __shared__ float ga_s[16], be_s[16];
    __shared__ float tile[16][68];
    #pragma unroll
    for (int o = 16; o; o >>= 1) {
        s  += __shfl_xor_sync(0xffffffffu, s, o);
        ss += __shfl_xor_sync(0xffffffffu, ss, o);
    }
    int wid = tid >> 5, lid = tid & 31;
    if (lid == 0) { rs_[wid] = s; rss_[wid] = ss; }
    __syncthreads();
    if (tid < 32) {
        s = rs_[lid & 7]; ss = rss_[lid & 7];
        #pragma unroll
        for (int o = 4; o; o >>= 1) {
            s  += __shfl_xor_sync(0xffffffffu, s, o);
            ss += __shfl_xor_sync(0xffffffffu, ss, o);
        }
        if (lid == 0) { rs_[0] = s; rss_[0] = ss; }
    }
    __syncthreads();
    float mean = rs_[0] * (1.f / 16384.f);
    float var  = rss_[0] * (1.f / 16384.f) - mean * mean;
    float inv  = rsqrtf(var + 1e-5f);
    if (tid < 16) {
        float ga = gamma[g * 16 + tid] * inv;
        ga_s[tid] = ga;
        be_s[tid] = beta[g * 16 + tid] - mean * ga;
    }
    __syncthreads();

    __half* outb = g_ht + (size_t)b * HWn * Cc + g * 16;
    int c = tid >> 4, q = tid & 15;
    int hw = tid >> 2, cq = tid & 3;
    for (int hw0 = 0; hw0 < HWn; hw0 += 64) {
        float4 v = xp[c * 256 + (hw0 >> 2) + q];
        float ga = ga_s[c], be = be_s[c];
        float4 o4;
        o4.x = v.x * ga + be; o4.y = v.y * ga + be;
        o4.z = v.z * ga + be; o4.w = v.w * ga + be;
        *(float4*)&tile[c][q << 2] = o4;
        __syncthreads();
        float4 w4;
        w4.x = tile[4 * cq + 0][hw];
        w4.y = tile[4 * cq + 1][hw];
        w4.z = tile[4 * cq + 2][hw];
        w4.w = tile[4 * cq + 3][hw];
        size_t off = (size_t)(hw0 + hw) * Cc + 4 * cq;
        *(__half2*)(outb + off)     = __floats2half2_rn(w4.x, w4.y);
        *(__half2*)(outb + off + 2) = __floats2half2_rn(w4.z, w4.w);
        __syncthreads();
    }
}

// ---------------------------------------------------------------------------
// Kernel 2: qkv GEMM (M = s rows of h^T, N = o rows of W).
// q,k -> [s][c] half2 stores; v -> transposed [c][s] scalar stores.
// ---------------------------------------------------------------------------
__global__ __launch_bounds__(256) void qkv_mma_kernel(const float* __restrict__ bias) {
    int b = blockIdx.z, m0 = blockIdx.x * 128, n0 = blockIdx.y * 128;
    const __half* Arow = g_ht + ((size_t)b * HWn + m0) * Cc;
    const __half* Brow = g_wqkv + (size_t)n0 * Cc;
    float acc[4][4][4];
    gemm_mainloop(Arow, Brow, acc);

    const int warp = threadIdx.x >> 5, lane = threadIdx.x & 31;
    const int wm = warp & 1, wn = warp >> 1;
    const int g = lane >> 2, tig = lane & 3;
    #pragma unroll
    for (int mi = 0; mi < 4; mi++) {
        #pragma unroll
        for (int h = 0; h < 2; h++) {
            int s = m0 + wm * 64 + mi * 16 + g + h * 8;
            #pragma unroll
            for (int ni = 0; ni < 4; ni++) {
                int o = n0 + wn * 32 + ni * 8 + 2 * tig;
                float2 bv = *(const float2*)&bias[o];
                float v0 = acc[mi][ni][h * 2 + 0] + bv.x;
                float v1 = acc[mi][ni][h * 2 + 1] + bv.y;
                int head = o / 192, rem = o - head * 192;
                int part = rem >> 6, c = rem & 63;
                __half* base = g_qkv + (size_t)((b * NH + head) * 3 + part) * HWn * DH;
                if (part < 2) {
                    *(__half2*)(base + (size_t)s * DH + c) = __floats2half2_rn(v0, v1);
                } else {
                    base[(size_t)c * HWn + s]       = __float2half_rn(v0);
                    base[(size_t)(c + 1) * HWn + s] = __float2half_rn(v1);
                }
            }
        }
    }
}

// ---------------------------------------------------------------------------
// Kernel 3: flash attention, fp16 HMMA + ldmatrix, 128-query blocks, 8 warps,
// 3-stage cp.async K/V. P stays in registers (acc layout == A-frag layout).
// Smem: Qs[128][72h] @0 (18432B), Ks[3][64][72h] @18432, Vt[3][64][72h] @46080.
// Total 73728 B -> 2 blocks/SM.
// ---------------------------------------------------------------------------
__global__ __launch_bounds__(256) void attn_mma_kernel() {
    extern __shared__ char asmem[];
    uint32_t sb = smem_u32(asmem);

    int bh = blockIdx.y;
    int q0 = blockIdx.x << 7;
    int tid = threadIdx.x;
    int w = tid >> 5, lane = tid & 31;
    int g = lane >> 2, tig = lane & 3;

    const __half* qp = g_qkv + ((size_t)bh * 3 * HWn + q0) * DH;
    const __half* kp = g_qkv + (size_t)(bh * 3 + 1) * HWn * DH;
    const __half* vp = g_qkv + (size_t)(bh * 3 + 2) * HWn * DH;  // [dh][s]
    const float scale = 0.044194173824159216f;   // 512^-0.5

    // ldmatrix lane addressing (row stride 144 B = 36 words, conflict-free)
    const int lrow = (lane & 7) + ((lane >> 3) & 1) * 8;
    const int lka  = ((lane >> 4) & 1) * 8;
    const int brow = (lane & 7) + ((lane >> 4) & 1) * 8;
    const int lkb  = ((lane >> 3) & 1) * 8;
    const uint32_t qAddr = sb + (uint32_t)((w * 16 + lrow) * 144 + lka * 2);
    const uint32_t kAddr = sb + (uint32_t)(18432 + brow * 144 + lkb * 2);
    const uint32_t vAddr = sb + (uint32_t)(46080 + brow * 144 + lkb * 2);

    // prologue: Q(128 rows) + tile0 K/V in group 0; tile1 K/V in group 1
    #pragma unroll
    for (int i = 0; i < 4; i++) {
        int id = tid + i * 256;
        int r = id >> 3, q = id & 7;
        CP16(sb + (uint32_t)(r * 144 + q * 16), qp + (size_t)r * DH + q * 8);
    }
    #pragma unroll
    for (int i = 0; i < 2; i++) {
        int id = tid + i * 256;
        int r = id >> 3, q = id & 7;
        CP16(sb + (uint32_t)(18432 + r * 144 + q * 16), kp + (size_t)r * DH + q * 8);
        CP16(sb + (uint32_t)(46080 + r * 144 + q * 16), vp + (size_t)r * HWn + q * 8);
    }
    CP_COMMIT();
    #pragma unroll
    for (int i = 0; i < 2; i++) {
        int id = tid + i * 256;
        int r = id >> 3, q = id & 7;
        CP16(sb + (uint32_t)(18432 + 9216 + r * 144 + q * 16),
             kp + (size_t)(64 + r) * DH + q * 8);
        CP16(sb + (uint32_t)(46080 + 9216 + r * 144 + q * 16),
             vp + (size_t)r * HWn + 64 + q * 8);
    }
    CP_COMMIT();

    float oacc[8][4];
    #pragma unroll
    for (int nd = 0; nd < 8; nd++)
        #pragma unroll
        for (int c = 0; c < 4; c++) oacc[nd][c] = 0.f;
    float m0 = -1e30f, m1 = -1e30f, l0 = 0.f, l1 = 0.f;

    #pragma unroll 1
    for (int t = 0; t < 16; t++) {
        if (t < 15) { CP_WAIT1(); } else { CP_WAIT0(); }
        __syncthreads();
        if (t + 2 < 16) {
            int st2 = (t + 2) % 3;
            const __half* kpt = kp + (size_t)(t + 2) * 64 * DH;
            const __half* vpt = vp + (t + 2) * 64;
            uint32_t ko = (uint32_t)(18432 + st2 * 9216);
            uint32_t vo = (uint32_t)(46080 + st2 * 9216);
            #pragma unroll
            for (int i = 0; i < 2; i++) {
                int id = tid + i * 256;
                int r = id >> 3, q = id & 7;
                CP16(sb + ko + (uint32_t)(r * 144 + q * 16), kpt + (size_t)r * DH + q * 8);
                CP16(sb + vo + (uint32_t)(r * 144 + q * 16), vpt + (size_t)r * HWn + q * 8);
            }
            CP_COMMIT();
        }
        const uint32_t so = (uint32_t)((t % 3) * 9216);

        // ---- S = Q @ K^T (16 q-rows x 64 keys per warp) ----
        float sacc[8][4];
        #pragma unroll
        for (int ni = 0; ni < 8; ni++)
            #pragma unroll
            for (int c = 0; c < 4; c++) sacc[ni][c] = 0.f;
        #pragma unroll
        for (int kk = 0; kk < 4; kk++) {
            uint32_t af[4];
            LDSM_X4(af[0], af[1], af[2], af[3], qAddr + kk * 32);
            #pragma unroll
            for (int p = 0; p < 4; p++) {
                uint32_t r0, r1, r2, r3;
                LDSM_X4(r0, r1, r2, r3, kAddr + so + p * 2304 + kk * 32);
                uint32_t b0[2] = {r0, r1}, b1[2] = {r2, r3};
                MMA_F16(sacc[2 * p],     af, b0);
                MMA_F16(sacc[2 * p + 1], af, b1);
            }
        }
        #pragma unroll
        for (int ni = 0; ni < 8; ni++)
            #pragma unroll
            for (int c = 0; c < 4; c++) sacc[ni][c] *= scale;

        // ---- online softmax (rows g, g+8) ----
        float mx0 = -1e30f, mx1 = -1e30f;
        #pragma unroll
        for (int ni = 0; ni < 8; ni++) {
            mx0 = fmaxf(mx0, fmaxf(sacc[ni][0], sacc[ni][1]));
            mx1 = fmaxf(mx1, fmaxf(sacc[ni][2], sacc[ni][3]));
        }
        mx0 = fmaxf(mx0, __shfl_xor_sync(0xffffffffu, mx0, 1));
        mx0 = fmaxf(mx0, __shfl_xor_sync(0xffffffffu, mx0, 2));
        mx1 = fmaxf(mx1, __shfl_xor_sync(0xffffffffu, mx1, 1));
        mx1 = fmaxf(mx1, __shfl_xor_sync(0xffffffffu, mx1, 2));
        float mn0 = fmaxf(m0, mx0), mn1 = fmaxf(m1, mx1);
        float al0 = __expf(m0 - mn0), al1 = __expf(m1 - mn1);
        float rs0 = 0.f, rs1 = 0.f;
        #pragma unroll
        for (int ni = 0; ni < 8; ni++) {
            sacc[ni][0] = __expf(sacc[ni][0] - mn0); rs0 += sacc[ni][0];
            sacc[ni][1] = __expf(sacc[ni][1] - mn0); rs0 += sacc[ni][1];
            sacc[ni][2] = __expf(sacc[ni][2] - mn1); rs1 += sacc[ni][2];
            sacc[ni][3] = __expf(sacc[ni][3] - mn1); rs1 += sacc[ni][3];
        }
        rs0 += __shfl_xor_sync(0xffffffffu, rs0, 1);
        rs0 += __shfl_xor_sync(0xffffffffu, rs0, 2);
        rs1 += __shfl_xor_sync(0xffffffffu, rs1, 1);
        rs1 += __shfl_xor_sync(0xffffffffu, rs1, 2);
        l0 = l0 * al0 + rs0; m0 = mn0;
        l1 = l1 * al1 + rs1; m1 = mn1;
        #pragma unroll
        for (int nd = 0; nd < 8; nd++) {
            oacc[nd][0] *= al0; oacc[nd][1] *= al0;
            oacc[nd][2] *= al1; oacc[nd][3] *= al1;
        }

        // ---- pack P to fp16 A-fragments IN REGISTERS (no smem round-trip) ----
        uint32_t ph[8][2];
        #pragma unroll
        for (int ni = 0; ni < 8; ni++) {
            ph[ni][0] = pack_h2(sacc[ni][0], sacc[ni][1]);   // row g
            ph[ni][1] = pack_h2(sacc[ni][2], sacc[ni][3]);   // row g+8
        }

        // ---- O += P @ V  (Vt = V^T [dh][key]) ----
        #pragma unroll
        for (int kk = 0; kk < 4; kk++) {
            uint32_t ap[4] = {ph[2 * kk][0], ph[2 * kk][1],
                              ph[2 * kk + 1][0], ph[2 * kk + 1][1]};
            #pragma unroll
            for (int p = 0; p < 4; p++) {
                uint32_t r0, r1, r2, r3;
                LDSM_X4(r0, r1, r2, r3, vAddr + so + p * 2304 + kk * 32);
                uint32_t b0[2] = {r0, r1}, b1[2] = {r2, r3};
                MMA_F16(oacc[2 * p],     ap, b0);
                MMA_F16(oacc[2 * p + 1], ap, b1);
            }
        }
    }

    // ---- epilogue: /l, head-major scramble, half2 stores ----
    float il0 = 1.f / l0, il1 = 1.f / l1;
    int bp  = bh & 15;
    int ch0 = (bh >> 4) << 6;
    int s0 = q0 + w * 16 + g;
    #pragma unroll
    for (int nd = 0; nd < 8; nd++) {
        int c = ch0 + nd * 8 + 2 * tig;
        *(__half2*)(g_attn + ((size_t)(bp * HWn + s0)) * Cc + c) =
            __floats2half2_rn(oacc[nd][0] * il0, oacc[nd][1] * il0);
        *(__half2*)(g_attn + ((size_t)(bp * HWn + s0 + 8)) * Cc + c) =
            __floats2half2_rn(oacc[nd][2] * il1, oacc[nd][3] * il1);
    }
}

// ---------------------------------------------------------------------------
// Kernel 4: out = W_proj @ attn + bias + x (fp32 out, residual).
// ---------------------------------------------------------------------------
__global__ __launch_bounds__(256) void proj_mma_kernel(const float* __restrict__ bias,
                                                       const float* __restrict__ x,
                                                       float* __restrict__ out) {
    int b = blockIdx.z, o0 = blockIdx.x * 128, n0 = blockIdx.y * 128;
    const __half* Arow = g_wproj + (size_t)o0 * Cc;
    const __half* Brow = g_attn + ((size_t)b * HWn + n0) * Cc;
    float acc[4][4][4];
    gemm_mainloop(Arow, Brow, acc);

    const int warp = threadIdx.x >> 5, lane = threadIdx.x & 31;
    const int wm = warp & 1, wn = warp >> 1;
    const int g = lane >> 2, tig = lane & 3;
    #pragma unroll
    for (int mi = 0; mi < 4; mi++) {
        #pragma unroll
        for (int h = 0; h < 2; h++) {
            int o = o0 + wm * 64 + mi * 16 + g + h * 8;
            float bv = __ldg(bias + o);
            size_t rowoff = (size_t)(b * Cc + o) * HWn;
            #pragma unroll
            for (int ni = 0; ni < 4; ni++) {
                int s = n0 + wn * 32 + ni * 8 + 2 * tig;
                float2 xv = *(const float2*)&x[rowoff + s];
                float2 ov;
                ov.x = acc[mi][ni][h * 2 + 0] + bv + xv.x;
                ov.y = acc[mi][ni][h * 2 + 1] + bv + xv.y;
                *(float2*)&out[rowoff + s] = ov;
            }
        }
    }
}

// ---------------------------------------------------------------------------
extern "C" void kernel_launch(void* const* d_in, const int* in_sizes, int n_in,
                              void* d_out, int out_size) {
    const float* x      = (const float*)d_in[0];
    const float* gamma  = (const float*)d_in[1];
    const float* beta   = (const float*)d_in[2];
    const float* w_qkv  = (const float*)d_in[3];
    const float* b_qkv  = (const float*)d_in[4];
    const float* w_proj = (const float*)d_in[5];
    const float* b_proj = (const float*)d_in[6];
    float* out = (float*)d_out;

    const int GEMM_SMEM = 61440;     // 3 stages x (A+B) x 128x80B
    const int ATTN_SMEM = 73728;     // Qs + 3x(Ks+Vt)
    cudaFuncSetAttribute(qkv_mma_kernel,
                         cudaFuncAttributeMaxDynamicSharedMemorySize, GEMM_SMEM);
    cudaFuncSetAttribute(proj_mma_kernel,
                         cudaFuncAttributeMaxDynamicSharedMemorySize, GEMM_SMEM);
    cudaFuncSetAttribute(attn_mma_kernel,
                         cudaFuncAttributeMaxDynamicSharedMemorySize, ATTN_SMEM);

    cvt_wqkv_kernel<<<768, 256>>>(w_qkv);
    cvt_wproj_kernel<<<256, 256>>>(w_proj);
    gn_kernel<<<Bn * 32, 256>>>(x, gamma, beta);
    qkv_mma_kernel<<<dim3(8, 12, Bn), 256, GEMM_SMEM>>>(b_qkv);
    attn_mma_kernel<<<dim3(HWn / 128, Bn * NH), 256, ATTN_SMEM>>>();
    proj_mma_kernel<<<dim3(4, 8, Bn), 256, GEMM_SMEM>>>(b_proj, x, out);
}

// round 8
// speedup vs baseline: 7.1107x; 1.0207x over previous
#include <cuda_runtime.h>
#include <cuda_fp16.h>
#include <cstdint>

#define Bn   16
#define Cc   512
#define HWn  1024
#define NH   8
#define DH   64

// Scratch (static device arrays — no cudaMalloc). All fp16.
__device__ __half g_ht[Bn * HWn * Cc];               // h^T  [b][hw][c]
__device__ __half g_qkv[Bn * NH * 3 * HWn * DH];     // q,k: [bh][p][s][c]; v: [bh][2][c][s]
__device__ __half g_attn[Bn * HWn * Cc];             // attn out [b][s][c]
__device__ __half g_wqkv[3 * Cc * Cc];               // fp16 copy of w_qkv
__device__ __half g_wproj[Cc * Cc];                  // fp16 copy of w_proj

// ---------------------------------------------------------------------------
// PTX helpers (sm_75/80-era — compile for plain sm_103 target)
// ---------------------------------------------------------------------------
__device__ __forceinline__ uint32_t smem_u32(const void* p) {
    uint32_t a;
    asm("{ .reg .u64 t; cvta.to.shared.u64 t, %1; cvt.u32.u64 %0, t; }" : "=r"(a) : "l"(p));
    return a;
}
#define CP16(dst, src)                                                        \
    asm volatile("cp.async.cg.shared.global [%0], [%1], 16;"                  \
                 :: "r"(dst), "l"(src))
#define CP_COMMIT() asm volatile("cp.async.commit_group;" ::: "memory")
#define CP_WAIT1()  asm volatile("cp.async.wait_group 1;" ::: "memory")
#define CP_WAIT0()  asm volatile("cp.async.wait_group 0;" ::: "memory")

#define LDSM_X4(r0, r1, r2, r3, a)                                            \
    asm volatile("ldmatrix.sync.aligned.m8n8.x4.shared.b16 {%0,%1,%2,%3}, [%4];" \
        : "=r"(r0), "=r"(r1), "=r"(r2), "=r"(r3) : "r"(a))

#define MMA_F16(c, a, bfr)                                                    \
    asm volatile(                                                             \
        "mma.sync.aligned.m16n8k16.row.col.f32.f16.f16.f32 "                  \
        "{%0,%1,%2,%3}, {%4,%5,%6,%7}, {%8,%9}, {%0,%1,%2,%3};"               \
        : "+f"((c)[0]), "+f"((c)[1]), "+f"((c)[2]), "+f"((c)[3])              \
        : "r"((a)[0]), "r"((a)[1]), "r"((a)[2]), "r"((a)[3]),                 \
          "r"((bfr)[0]), "r"((bfr)[1]))

__device__ __forceinline__ uint32_t pack_h2(float lo, float hi) {
    __half2 h = __floats2half2_rn(lo, hi);
    uint32_t u;
    memcpy(&u, &h, 4);
    return u;
}

// ---------------------------------------------------------------------------
// Weight fp32 -> fp16 converter (both weights, one launch)
// ---------------------------------------------------------------------------
__global__ __launch_bounds__(256) void cvt_w_kernel(const float* __restrict__ wq,
                                                    const float* __restrict__ wp) {
    int i = (blockIdx.x * 256 + threadIdx.x) * 4;
    if (i < 3 * Cc * Cc) {
        float4 v = *(const float4*)(wq + i);
        *(__half2*)(g_wqkv + i)     = __floats2half2_rn(v.x, v.y);
        *(__half2*)(g_wqkv + i + 2) = __floats2half2_rn(v.z, v.w);
    } else {
        int j = i - 3 * Cc * Cc;
        float4 v = *(const float4*)(wp + j);
        *(__half2*)(g_wproj + j)     = __floats2half2_rn(v.x, v.y);
        *(__half2*)(g_wproj + j + 2) = __floats2half2_rn(v.z, v.w);
    }
}

// ---------------------------------------------------------------------------
// fp16 warp-MMA GEMM mainloop, cp.async 3-stage, ldmatrix, k-tile 64 halves.
// D[128x128] = A[128x512] * B[128x512]^T, both K-major fp16.
// 8 warps (2m x 4n), warp tile 64x32. Row = 128B data + 16B pad (stride 144B).
// Stage = (A 128 + B 128 rows) x 144B = 36864 B; 3 stages = 110592 B.
// 8 k-tiles -> 8 barriers per block (vs 16 at k-tile 32).
// ---------------------------------------------------------------------------
__device__ __forceinline__ void gemm_fill(uint32_t sb, int st,
                                          const __half* __restrict__ Arow,
                                          const __half* __restrict__ Brow,
                                          int k0, int tid) {
    const uint32_t so = sb + (uint32_t)st * 36864u;
    #pragma unroll
    for (int i = 0; i < 4; i++) {
        int id = tid + i * 256;           // 0..1023
        int r = id >> 3, q = id & 7;      // 128 rows x 8x16B
        CP16(so + (uint32_t)(r * 144 + q * 16),
             Arow + (size_t)r * Cc + k0 + q * 8);
        CP16(so + 18432u + (uint32_t)(r * 144 + q * 16),
             Brow + (size_t)r * Cc + k0 + q * 8);
    }
}

__device__ __forceinline__ void gemm_mainloop(const __half* __restrict__ Arow,
                                              const __half* __restrict__ Brow,
                                              float acc[4][4][4]) {
    extern __shared__ char gsm[];
    uint32_t sb = smem_u32(gsm);
    const int tid = threadIdx.x;
    const int warp = tid >> 5, lane = tid & 31;
    const int wm = warp & 1, wn = warp >> 1;
    const int lrow = (lane & 7) + ((lane >> 3) & 1) * 8;   // A: m within 16
    const int lka  = ((lane >> 4) & 1) * 8;                // A: k halves
    const int brow = (lane & 7) + ((lane >> 4) & 1) * 8;   // B: n within 16
    const int lkb  = ((lane >> 3) & 1) * 8;
    const uint32_t aBase = sb + (uint32_t)((wm * 64 + lrow) * 144 + lka * 2);
    const uint32_t bBase = sb + 18432u + (uint32_t)((wn * 32 + brow) * 144 + lkb * 2);

    #pragma unroll
    for (int mi = 0; mi < 4; mi++)
        #pragma unroll
        for (int ni = 0; ni < 4; ni++)
            #pragma unroll
            for (int c = 0; c < 4; c++) acc[mi][ni][c] = 0.f;

    gemm_fill(sb, 0, Arow, Brow, 0, tid);
    CP_COMMIT();
    gemm_fill(sb, 1, Arow, Brow, 64, tid);
    CP_COMMIT();

    #pragma unroll 1
    for (int it = 0; it < 8; it++) {
        if (it < 7) { CP_WAIT1(); } else { CP_WAIT0(); }
        __syncthreads();
        if (it + 2 < 8) {
            gemm_fill(sb, (it + 2) % 3, Arow, Brow, (it + 2) * 64, tid);
            CP_COMMIT();
        }
        const uint32_t so = (uint32_t)((it % 3) * 36864);
        #pragma unroll
        for (int kk = 0; kk < 4; kk++) {
            uint32_t af[4][4], bf[4][2];
            #pragma unroll
            for (int mi = 0; mi < 4; mi++)
                LDSM_X4(af[mi][0], af[mi][1], af[mi][2], af[mi][3],
                        aBase + so + mi * 2304 + kk * 32);
            #pragma unroll
            for (int p = 0; p < 2; p++) {
                uint32_t r0, r1, r2, r3;
                LDSM_X4(r0, r1, r2, r3, bBase + so + p * 2304 + kk * 32);
                bf[2 * p][0] = r0; bf[2 * p][1] = r1;
                bf[2 * p + 1][0] = r2; bf[2 * p + 1][1] = r3;
            }
            #pragma unroll
            for (int mi = 0; mi < 4; mi++)
                #pragma unroll
                for (int ni = 0; ni < 4; ni++)
                    MMA_F16(acc[mi][ni], af[mi], bf[ni]);
        }
    }
}

// ---------------------------------------------------------------------------
// Kernel 1: GroupNorm -> g_ht[b][hw][c] (fp16). Single-tile, 3 barriers.
// Dyn smem: sx[16][1032] fp32 = 66048 B.
// ---------------------------------------------------------------------------
__global__ __launch_bounds__(256) void gn_kernel(const float* __restrict__ x,
                                                 const float* __restrict__ gamma,
                                                 const float* __restrict__ beta) {
    extern __shared__ float sx[];            // [16][1032]
    __shared__ float rs_[8], rss_[8];
    __shared__ float ga_s[16], be_s[16];

    int b = blockIdx.x >> 5;
    int g = blockIdx.x & 31;
    int tid = threadIdx.x;
    size_t base = (size_t)(b * Cc + g * 16) * HWn;
    const float4* xp = (const float4*)(x + base);

    float s = 0.f, ss = 0.f;
    for (int i = tid; i < 4096; i += 256) {
        float4 v = xp[i];
        int c = i >> 8, hw4 = i & 255;
        *(float4*)&sx[c * 1032 + hw4 * 4] = v;
        s  += v.x + v.y + v.z + v.w;
        ss += v.x * v.x + v.y * v.y + v.z * v.z + v.w * v.w;
    }
    #pragma unroll
    for (int o = 16; o; o >>= 1) {
        s  += __shfl_xor_sync(0xffffffffu, s, o);
        ss += __shfl_xor_sync(0xffffffffu, ss, o);
    }
    int wid = tid >> 5, lid = tid & 31;
    if (lid == 0) { rs_[wid] = s; rss_[wid] = ss; }
    __syncthreads();
    if (tid < 32) {
        s = rs_[lid & 7]; ss = rss_[lid & 7];
        #pragma unroll
        for (int o = 4; o; o >>= 1) {
            s  += __shfl_xor_sync(0xffffffffu, s, o);
            ss += __shfl_xor_sync(0xffffffffu, ss, o);
        }
        if (lid == 0) { rs_[0] = s; rss_[0] = ss; }
    }
    __syncthreads();
    float mean = rs_[0] * (1.f / 16384.f);
    float var  = rss_[0] * (1.f / 16384.f) - mean * mean;
    float inv  = rsqrtf(var + 1e-5f);
    if (tid < 16) {
        float ga = gamma[g * 16 + tid] * inv;
        ga_s[tid] = ga;
        be_s[tid] = beta[g * 16 + tid] - mean * ga;
    }
    __syncthreads();

    __half* outb = g_ht + (size_t)b * HWn * Cc + g * 16;
    for (int hw = tid; hw < HWn; hw += 256) {
        uint32_t pk[8];
        #pragma unroll
        for (int cp = 0; cp < 8; cp++) {
            float v0 = sx[(2 * cp) * 1032 + hw]     * ga_s[2 * cp]     + be_s[2 * cp];
            float v1 = sx[(2 * cp + 1) * 1032 + hw] * ga_s[2 * cp + 1] + be_s[2 * cp + 1];
            pk[cp] = pack_h2(v0, v1);
        }
        __half* dst = outb + (size_t)hw * Cc;
        *(uint4*)dst       = make_uint4(pk[0], pk[1], pk[2], pk[3]);
        *(uint4*)(dst + 8) = make_uint4(pk[4], pk[5], pk[6], pk[7]);
    }
}

// ---------------------------------------------------------------------------
// Kernel 2: qkv GEMM (M = s rows of h^T, N = o rows of W).
// q,k -> [s][c] half2 stores; v -> transposed [c][s] scalar stores.
// ---------------------------------------------------------------------------
__global__ __launch_bounds__(256) void qkv_mma_kernel(const float* __restrict__ bias) {
    int b = blockIdx.z, m0 = blockIdx.x * 128, n0 = blockIdx.y * 128;
    const __half* Arow = g_ht + ((size_t)b * HWn + m0) * Cc;
    const __half* Brow = g_wqkv + (size_t)n0 * Cc;
    float acc[4][4][4];
    gemm_mainloop(Arow, Brow, acc);

    const int warp = threadIdx.x >> 5, lane = threadIdx.x & 31;
    const int wm = warp & 1, wn = warp >> 1;
    const int g = lane >> 2, tig = lane & 3;
    #pragma unroll
    for (int mi = 0; mi < 4; mi++) {
        #pragma unroll
        for (int h = 0; h < 2; h++) {
            int s = m0 + wm * 64 + mi * 16 + g + h * 8;
            #pragma unroll
            for (int ni = 0; ni < 4; ni++) {
                int o = n0 + wn * 32 + ni * 8 + 2 * tig;
                float2 bv = *(const float2*)&bias[o];
                float v0 = acc[mi][ni][h * 2 + 0] + bv.x;
                float v1 = acc[mi][ni][h * 2 + 1] + bv.y;
                int head = o / 192, rem = o - head * 192;
                int part = rem >> 6, c = rem & 63;
                __half* base = g_qkv + (size_t)((b * NH + head) * 3 + part) * HWn * DH;
                if (part < 2) {
                    *(__half2*)(base + (size_t)s * DH + c) = __floats2half2_rn(v0, v1);
                } else {
                    base[(size_t)c * HWn + s]       = __float2half_rn(v0);
                    base[(size_t)(c + 1) * HWn + s] = __float2half_rn(v1);
                }
            }
        }
    }
}

// ---------------------------------------------------------------------------
// Kernel 3: flash attention, fp16 HMMA + ldmatrix, 128-query blocks, 8 warps,
// 3-stage cp.async K/V. P stays in registers.
// Smem: Qs[128][72h] @0 (18432B), Ks[3][64][72h] @18432, Vt[3][64][72h] @46080.
// Total 73728 B -> 2 blocks/SM.
// ---------------------------------------------------------------------------
__global__ __launch_bounds__(256) void attn_mma_kernel() {
    extern __shared__ char asmem[];
    uint32_t sb = smem_u32(asmem);

    int bh = blockIdx.y;
    int q0 = blockIdx.x << 7;
    int tid = threadIdx.x;
    int w = tid >> 5, lane = tid & 31;
    int g = lane >> 2, tig = lane & 3;

    const __half* qp = g_qkv + ((size_t)bh * 3 * HWn + q0) * DH;
    const __half* kp = g_qkv + (size_t)(bh * 3 + 1) * HWn * DH;
    const __half* vp = g_qkv + (size_t)(bh * 3 + 2) * HWn * DH;  // [dh][s]
    const float scale = 0.044194173824159216f;   // 512^-0.5

    const int lrow = (lane & 7) + ((lane >> 3) & 1) * 8;
    const int lka  = ((lane >> 4) & 1) * 8;
    const int brow = (lane & 7) + ((lane >> 4) & 1) * 8;
    const int lkb  = ((lane >> 3) & 1) * 8;
    const uint32_t qAddr = sb + (uint32_t)((w * 16 + lrow) * 144 + lka * 2);
    const uint32_t kAddr = sb + (uint32_t)(18432 + brow * 144 + lkb * 2);
    const uint32_t vAddr = sb + (uint32_t)(46080 + brow * 144 + lkb * 2);

    #pragma unroll
    for (int i = 0; i < 4; i++) {
        int id = tid + i * 256;
        int r = id >> 3, q = id & 7;
        CP16(sb + (uint32_t)(r * 144 + q * 16), qp + (size_t)r * DH + q * 8);
    }
    #pragma unroll
    for (int i = 0; i < 2; i++) {
        int id = tid + i * 256;
        int r = id >> 3, q = id & 7;
        CP16(sb + (uint32_t)(18432 + r * 144 + q * 16), kp + (size_t)r * DH + q * 8);
        CP16(sb + (uint32_t)(46080 + r * 144 + q * 16), vp + (size_t)r * HWn + q * 8);
    }
    CP_COMMIT();
    #pragma unroll
    for (int i = 0; i < 2; i++) {
        int id = tid + i * 256;
        int r = id >> 3, q = id & 7;
        CP16(sb + (uint32_t)(18432 + 9216 + r * 144 + q * 16),
             kp + (size_t)(64 + r) * DH + q * 8);
        CP16(sb + (uint32_t)(46080 + 9216 + r * 144 + q * 16),
             vp + (size_t)r * HWn + 64 + q * 8);
    }
    CP_COMMIT();

    float oacc[8][4];
    #pragma unroll
    for (int nd = 0; nd < 8; nd++)
        #pragma unroll
        for (int c = 0; c < 4; c++) oacc[nd][c] = 0.f;
    float m0 = -1e30f, m1 = -1e30f, l0 = 0.f, l1 = 0.f;

    #pragma unroll 1
    for (int t = 0; t < 16; t++) {
        if (t < 15) { CP_WAIT1(); } else { CP_WAIT0(); }
        __syncthreads();
        if (t + 2 < 16) {
            int st2 = (t + 2) % 3;
            const __half* kpt = kp + (size_t)(t + 2) * 64 * DH;
            const __half* vpt = vp + (t + 2) * 64;
            uint32_t ko = (uint32_t)(18432 + st2 * 9216);
            uint32_t vo = (uint32_t)(46080 + st2 * 9216);
            #pragma unroll
            for (int i = 0; i < 2; i++) {
                int id = tid + i * 256;
                int r = id >> 3, q = id & 7;
                CP16(sb + ko + (uint32_t)(r * 144 + q * 16), kpt + (size_t)r * DH + q * 8);
                CP16(sb + vo + (uint32_t)(r * 144 + q * 16), vpt + (size_t)r * HWn + q * 8);
            }
            CP_COMMIT();
        }
        const uint32_t so = (uint32_t)((t % 3) * 9216);

        // ---- S = Q @ K^T ----
        float sacc[8][4];
        #pragma unroll
        for (int ni = 0; ni < 8; ni++)
            #pragma unroll
            for (int c = 0; c < 4; c++) sacc[ni][c] = 0.f;
        #pragma unroll
        for (int kk = 0; kk < 4; kk++) {
            uint32_t af[4];
            LDSM_X4(af[0], af[1], af[2], af[3], qAddr + kk * 32);
            #pragma unroll
            for (int p = 0; p < 4; p++) {
                uint32_t r0, r1, r2, r3;
                LDSM_X4(r0, r1, r2, r3, kAddr + so + p * 2304 + kk * 32);
                uint32_t b0[2] = {r0, r1}, b1[2] = {r2, r3};
                MMA_F16(sacc[2 * p],     af, b0);
                MMA_F16(sacc[2 * p + 1], af, b1);
            }
        }
        #pragma unroll
        for (int ni = 0; ni < 8; ni++)
            #pragma unroll
            for (int c = 0; c < 4; c++) sacc[ni][c] *= scale;

        // ---- online softmax (rows g, g+8) ----
        float mx0 = -1e30f, mx1 = -1e30f;
        #pragma unroll
        for (int ni = 0; ni < 8; ni++) {
            mx0 = fmaxf(mx0, fmaxf(sacc[ni][0], sacc[ni][1]));
            mx1 = fmaxf(mx1, fmaxf(sacc[ni][2], sacc[ni][3]));
        }
        mx0 = fmaxf(mx0, __shfl_xor_sync(0xffffffffu, mx0, 1));
        mx0 = fmaxf(mx0, __shfl_xor_sync(0xffffffffu, mx0, 2));
        mx1 = fmaxf(mx1, __shfl_xor_sync(0xffffffffu, mx1, 1));
        mx1 = fmaxf(mx1, __shfl_xor_sync(0xffffffffu, mx1, 2));
        float mn0 = fmaxf(m0, mx0), mn1 = fmaxf(m1, mx1);
        float al0 = __expf(m0 - mn0), al1 = __expf(m1 - mn1);
        float rs0 = 0.f, rs1 = 0.f;
        #pragma unroll
        for (int ni = 0; ni < 8; ni++) {
            sacc[ni][0] = __expf(sacc[ni][0] - mn0); rs0 += sacc[ni][0];
            sacc[ni][1] = __expf(sacc[ni][1] - mn0); rs0 += sacc[ni][1];
            sacc[ni][2] = __expf(sacc[ni][2] - mn1); rs1 += sacc[ni][2];
            sacc[ni][3] = __expf(sacc[ni][3] - mn1); rs1 += sacc[ni][3];
        }
        rs0 += __shfl_xor_sync(0xffffffffu, rs0, 1);
        rs0 += __shfl_xor_sync(0xffffffffu, rs0, 2);
        rs1 += __shfl_xor_sync(0xffffffffu, rs1, 1);
        rs1 += __shfl_xor_sync(0xffffffffu, rs1, 2);
        l0 = l0 * al0 + rs0; m0 = mn0;
        l1 = l1 * al1 + rs1; m1 = mn1;
        #pragma unroll
        for (int nd = 0; nd < 8; nd++) {
            oacc[nd][0] *= al0; oacc[nd][1] *= al0;
            oacc[nd][2] *= al1; oacc[nd][3] *= al1;
        }

        // ---- pack P to fp16 A-fragments in registers ----
        uint32_t ph[8][2];
        #pragma unroll
        for (int ni = 0; ni < 8; ni++) {
            ph[ni][0] = pack_h2(sacc[ni][0], sacc[ni][1]);
            ph[ni][1] = pack_h2(sacc[ni][2], sacc[ni][3]);
        }

        // ---- O += P @ V ----
        #pragma unroll
        for (int kk = 0; kk < 4; kk++) {
            uint32_t ap[4] = {ph[2 * kk][0], ph[2 * kk][1],
                              ph[2 * kk + 1][0], ph[2 * kk + 1][1]};
            #pragma unroll
            for (int p = 0; p < 4; p++) {
                uint32_t r0, r1, r2, r3;
                LDSM_X4(r0, r1, r2, r3, vAddr + so + p * 2304 + kk * 32);
                uint32_t b0[2] = {r0, r1}, b1[2] = {r2, r3};
                MMA_F16(oacc[2 * p],     ap, b0);
                MMA_F16(oacc[2 * p + 1], ap, b1);
            }
        }
    }

    // ---- epilogue ----
    float il0 = 1.f / l0, il1 = 1.f / l1;
    int bp  = bh & 15;
    int ch0 = (bh >> 4) << 6;
    int s0 = q0 + w * 16 + g;
    #pragma unroll
    for (int nd = 0; nd < 8; nd++) {
        int c = ch0 + nd * 8 + 2 * tig;
        *(__half2*)(g_attn + ((size_t)(bp * HWn + s0)) * Cc + c) =
            __floats2half2_rn(oacc[nd][0] * il0, oacc[nd][1] * il0);
        *(__half2*)(g_attn + ((size_t)(bp * HWn + s0 + 8)) * Cc + c) =
            __floats2half2_rn(oacc[nd][2] * il1, oacc[nd][3] * il1);
    }
}

// ---------------------------------------------------------------------------
// Kernel 4: out = W_proj @ attn + bias + x (fp32 out, residual).
// ---------------------------------------------------------------------------
__global__ __launch_bounds__(256) void proj_mma_kernel(const float* __restrict__ bias,
                                                       const float* __restrict__ x,
                                                       float* __restrict__ out) {
    int b = blockIdx.z, o0 = blockIdx.x * 128, n0 = blockIdx.y * 128;
    const __half* Arow = g_wproj + (size_t)o0 * Cc;
    const __half* Brow = g_attn + ((size_t)b * HWn + n0) * Cc;
    float acc[4][4][4];
    gemm_mainloop(Arow, Brow, acc);

    const int warp = threadIdx.x >> 5, lane = threadIdx.x & 31;
    const int wm = warp & 1, wn = warp >> 1;
    const int g = lane >> 2, tig = lane & 3;
    #pragma unroll
    for (int mi = 0; mi < 4; mi++) {
        #pragma unroll
        for (int h = 0; h < 2; h++) {
            int o = o0 + wm * 64 + mi * 16 + g + h * 8;
            float bv = __ldg(bias + o);
            size_t rowoff = (size_t)(b * Cc + o) * HWn;
            #pragma unroll
            for (int ni = 0; ni < 4; ni++) {
                int s = n0 + wn * 32 + ni * 8 + 2 * tig;
                float2 xv = *(const float2*)&x[rowoff + s];
                float2 ov;
                ov.x = acc[mi][ni][h * 2 + 0] + bv + xv.x;
                ov.y = acc[mi][ni][h * 2 + 1] + bv + xv.y;
                *(float2*)&out[rowoff + s] = ov;
            }
        }
    }
}

// ---------------------------------------------------------------------------
extern "C" void kernel_launch(void* const* d_in, const int* in_sizes, int n_in,
                              void* d_out, int out_size) {
    const float* x      = (const float*)d_in[0];
    const float* gamma  = (const float*)d_in[1];
    const float* beta   = (const float*)d_in[2];
    const float* w_qkv  = (const float*)d_in[3];
    const float* b_qkv  = (const float*)d_in[4];
    const float* w_proj = (const float*)d_in[5];
    const float* b_proj = (const float*)d_in[6];
    float* out = (float*)d_out;

    const int GEMM_SMEM = 110592;    // 3 stages x (A+B) x 128x144B
    const int ATTN_SMEM = 73728;
    const int GN_SMEM   = 66048;     // 16 x 1032 fp32
    cudaFuncSetAttribute(qkv_mma_kernel,
                         cudaFuncAttributeMaxDynamicSharedMemorySize, GEMM_SMEM);
    cudaFuncSetAttribute(proj_mma_kernel,
                         cudaFuncAttributeMaxDynamicSharedMemorySize, GEMM_SMEM);
    cudaFuncSetAttribute(attn_mma_kernel,
                         cudaFuncAttributeMaxDynamicSharedMemorySize, ATTN_SMEM);
    cudaFuncSetAttribute(gn_kernel,
                         cudaFuncAttributeMaxDynamicSharedMemorySize, GN_SMEM);

    cvt_w_kernel<<<1024, 256>>>(w_qkv, w_proj);
    gn_kernel<<<Bn * 32, 256, GN_SMEM>>>(x, gamma, beta);
    qkv_mma_kernel<<<dim3(8, 12, Bn), 256, GEMM_SMEM>>>(b_qkv);
    attn_mma_kernel<<<dim3(HWn / 128, Bn * NH), 256, ATTN_SMEM>>>();
    proj_mma_kernel<<<dim3(4, 8, Bn), 256, GEMM_SMEM>>>(b_proj, x, out);
}